// round 15
// baseline (speedup 1.0000x reference)
#include <cuda_runtime.h>
#include <cuda_bf16.h>
#include <math.h>
#include <stdint.h>

// Problem constants
#define BQ   2048
#define TQ   16
#define DQ   2048
#define DHQ  1024
#define NCQ  174
#define DTQ  32768          // D*T
#define RWS  4096           // 2*DH + D  (theta; phi; M rows)
#define NTOT 32768          // B*T columns
#define CRW  65536          // per-batch C stride (4096*16)

// GEMM tiling
#define MT     128
#define NT     256
#define KC     32
#define NCH    (DQ / KC)    // 64
#define STAGES 3
#define APL    8192                    // A plane tile: 128 rows * 64B
#define BPL    16384                   // B plane tile: 256 rows * 64B
#define BOFF   (3 * APL)               // 24576
#define STB    (3 * APL + 3 * BPL)     // 73728
#define SMEMT  (STAGES * STB)          // 221184

// fc1 split-K
#define FC1KS  4
#define FC1KC  (DTQ / FC1KS)           // 8192

// ---------------- device scratch ----------------
__device__ float g_inv [DQ];
__device__ float g_cadd[DQ];
__device__ float g_cc  [DQ];
__device__ float g_M   [(size_t)DQ * DQ];       // W_w @ g_w
__device__ float g_bc  [RWS];
__device__ float g_alpha[(size_t)BQ * 256];     // softmax alpha per batch [t][s]
__device__ __nv_bfloat16 g_Wp1[(size_t)RWS * DQ];   // folded weight planes
__device__ __nv_bfloat16 g_Wp2[(size_t)RWS * DQ];
__device__ __nv_bfloat16 g_Wp3[(size_t)RWS * DQ];
__device__ __nv_bfloat16 g_Hp1[(size_t)NTOT * DQ];  // h planes [n=b*16+t][k=d]
__device__ __nv_bfloat16 g_Hp2[(size_t)NTOT * DQ];
__device__ __nv_bfloat16 g_Hp3[(size_t)NTOT * DQ];
__device__ float g_C   [(size_t)BQ * CRW];      // projections [b][o][t]
__device__ float g_F   [(size_t)BQ * DTQ];
__device__ float g_Y1  [(size_t)BQ * 512];
__device__ float g_Y1p [FC1KS][(size_t)BQ * 512];   // fc1 K-split partials

// ---------------- helpers ----------------
__device__ __forceinline__ uint32_t smem_u32(const void* p) {
    uint32_t a;
    asm("{ .reg .u64 t; cvta.to.shared.u64 t, %1; cvt.u32.u64 %0, t; }" : "=r"(a) : "l"(p));
    return a;
}

__device__ __forceinline__ void cp16(uint32_t dst, const void* src) {
    asm volatile("cp.async.cg.shared.global [%0], [%1], 16;" :: "r"(dst), "l"(src));
}
#define CP_COMMIT() asm volatile("cp.async.commit_group;" ::: "memory")
#define CP_WAIT1()  asm volatile("cp.async.wait_group 1;" ::: "memory")

__device__ __forceinline__ void ldm_x4(uint32_t* r, uint32_t addr) {
    asm volatile("ldmatrix.sync.aligned.m8n8.x4.shared.b16 {%0,%1,%2,%3}, [%4];"
                 : "=r"(r[0]), "=r"(r[1]), "=r"(r[2]), "=r"(r[3]) : "r"(addr));
}

__device__ __forceinline__ void mma16(float* c, const uint32_t* a, uint32_t b0, uint32_t b1) {
    asm volatile("mma.sync.aligned.m16n8k16.row.col.f32.bf16.bf16.f32 "
                 "{%0,%1,%2,%3},{%4,%5,%6,%7},{%8,%9},{%0,%1,%2,%3};"
                 : "+f"(c[0]), "+f"(c[1]), "+f"(c[2]), "+f"(c[3])
                 : "r"(a[0]), "r"(a[1]), "r"(a[2]), "r"(a[3]), "r"(b0), "r"(b1));
}

// 3-way bf16 split: v ~= b1 + b2 + b3
__device__ __forceinline__ void bsplit(float v, uint16_t& o1, uint16_t& o2, uint16_t& o3) {
    __nv_bfloat16 x1 = __float2bfloat16_rn(v);
    float r1 = v - __bfloat162float(x1);
    __nv_bfloat16 x2 = __float2bfloat16_rn(r1);
    float r2 = r1 - __bfloat162float(x2);
    __nv_bfloat16 x3 = __float2bfloat16_rn(r2);
    o1 = *(uint16_t*)&x1;
    o2 = *(uint16_t*)&x2;
    o3 = *(uint16_t*)&x3;
}

__device__ __forceinline__ float bf2f(uint16_t u) {
    __nv_bfloat16 h = *(__nv_bfloat16*)&u;
    return __bfloat162float(h);
}

__device__ __forceinline__ void load4(const __nv_bfloat16* p, float* f) {
    uint2 u = *(const uint2*)p;
    const uint16_t* h = (const uint16_t*)&u;
    f[0] = bf2f(h[0]); f[1] = bf2f(h[1]); f[2] = bf2f(h[2]); f[3] = bf2f(h[3]);
}

// 64B-row XOR swizzle: conflict-free for 8-row ldmatrix and 16B fills
__device__ __forceinline__ uint32_t sw64(int row, int g) {
    return (uint32_t)(row * 64 + ((g ^ ((row >> 1) & 3)) << 4));
}

// ---------------- prep kernels ----------------
__global__ void k_bn_prep(const float* __restrict__ gamma, const float* __restrict__ beta,
                          const float* __restrict__ mean,  const float* __restrict__ var) {
    int d = blockIdx.x * blockDim.x + threadIdx.x;
    if (d < DQ) {
        float inv = gamma[d] * rsqrtf(var[d] + 1e-5f);
        float ca  = beta[d] - mean[d] * inv;
        g_inv[d]  = inv;
        g_cadd[d] = ca;
        g_cc[d]   = ca * (2.0f * inv + 1.0f);
    }
}

__global__ __launch_bounds__(256) void k_foldbias(
    const float* __restrict__ thw, const float* __restrict__ phw,
    const float* __restrict__ gamma, const float* __restrict__ beta,
    const float* __restrict__ mean,  const float* __restrict__ var) {
    const int o = blockIdx.x;
    const int tid = threadIdx.x;
    const float* row;
    if (o < 1024)      row = thw + (size_t)o * DQ;
    else if (o < 2048) row = phw + (size_t)(o - 1024) * DQ;
    else               row = g_M + (size_t)(o - 2048) * DQ;
    float accb = 0.f;
    for (int d = tid; d < DQ; d += 256) {
        float inv = gamma[d] * rsqrtf(var[d] + 1e-5f);
        float ca  = beta[d] - mean[d] * inv;
        float w   = row[d];
        float v   = w * inv;
        uint16_t b1, b2, b3;
        bsplit(v, b1, b2, b3);
        size_t idx = (size_t)o * DQ + d;
        *(uint16_t*)&g_Wp1[idx] = b1;
        *(uint16_t*)&g_Wp2[idx] = b2;
        *(uint16_t*)&g_Wp3[idx] = b3;
        accb += w * ca;
    }
    __shared__ float red[256];
    red[tid] = accb;
    __syncthreads();
    for (int st = 128; st > 0; st >>= 1) {
        if (tid < st) red[tid] += red[tid + st];
        __syncthreads();
    }
    if (tid == 0) g_bc[o] = red[0];
}

// Ht planes[n=b*16+t][k=d] = split(x[b*32768 + d*16 + t])
__global__ __launch_bounds__(256) void k_init(const float* __restrict__ x) {
    __shared__ float s[128 * 17];
    int b = blockIdx.x, tid = threadIdx.x;
    for (int d0 = 0; d0 < DQ; d0 += 128) {
        for (int i = tid; i < 2048; i += 256) {
            int dd = i >> 4, t = i & 15;
            s[dd * 17 + t] = x[(size_t)b * DTQ + d0 * 16 + i];
        }
        __syncthreads();
        int t = tid >> 4, j = tid & 15;
        size_t base = ((size_t)(b * 16 + t)) * DQ + d0 + j * 8;
#pragma unroll
        for (int i = 0; i < 8; i += 2) {
            float v0 = s[(j * 8 + i) * 17 + t];
            float v1 = s[(j * 8 + i + 1) * 17 + t];
            uint16_t a1, a2, a3, c1, c2, c3;
            bsplit(v0, a1, a2, a3);
            bsplit(v1, c1, c2, c3);
            *(uint32_t*)&g_Hp1[base + i] = (uint32_t)a1 | ((uint32_t)c1 << 16);
            *(uint32_t*)&g_Hp2[base + i] = (uint32_t)a2 | ((uint32_t)c2 << 16);
            *(uint32_t*)&g_Hp3[base + i] = (uint32_t)a3 | ((uint32_t)c3 << 16);
        }
        __syncthreads();
    }
}

// ---------------- M = W_w @ g_w (fp32 SIMT, run once) ----------------
__global__ __launch_bounds__(256) void k_gemm_M(const float* __restrict__ A,
                                                const float* __restrict__ B) {
    __shared__ float As[16][132];
    __shared__ float Bs[16][132];
    const int tid = threadIdx.x;
    const int rx  = tid & 15;
    const int ry  = tid >> 4;
    const int row0 = blockIdx.y * 128;
    const int col0 = blockIdx.x * 128;
    float acc[8][8];
#pragma unroll
    for (int i = 0; i < 8; i++)
#pragma unroll
        for (int j = 0; j < 8; j++) acc[i][j] = 0.f;
    for (int k0 = 0; k0 < DHQ; k0 += 16) {
#pragma unroll
        for (int f = tid; f < 512; f += 256) {
            int r = f >> 2, kk = (f & 3) << 2;
            float4 v = *(const float4*)(&A[(size_t)(row0 + r) * DHQ + k0 + kk]);
            As[kk + 0][r] = v.x; As[kk + 1][r] = v.y;
            As[kk + 2][r] = v.z; As[kk + 3][r] = v.w;
        }
#pragma unroll
        for (int f = tid; f < 512; f += 256) {
            int k = f >> 5, cc = (f & 31) << 2;
            float4 v = *(const float4*)(&B[(size_t)(k0 + k) * DQ + col0 + cc]);
            *(float4*)(&Bs[k][cc]) = v;
        }
        __syncthreads();
#pragma unroll
        for (int k = 0; k < 16; k++) {
            float ra[8], rb[8];
            *(float4*)(ra)     = *(const float4*)(&As[k][ry * 4]);
            *(float4*)(ra + 4) = *(const float4*)(&As[k][64 + ry * 4]);
            *(float4*)(rb)     = *(const float4*)(&Bs[k][rx * 4]);
            *(float4*)(rb + 4) = *(const float4*)(&Bs[k][64 + rx * 4]);
#pragma unroll
            for (int i = 0; i < 8; i++)
#pragma unroll
                for (int j = 0; j < 8; j++) acc[i][j] += ra[i] * rb[j];
        }
        __syncthreads();
    }
#pragma unroll
    for (int ih = 0; ih < 2; ih++)
#pragma unroll
        for (int i = 0; i < 4; i++) {
            const int r = row0 + ih * 64 + ry * 4 + i;
#pragma unroll
            for (int jh = 0; jh < 2; jh++) {
                const int c = col0 + jh * 64 + rx * 4;
                float4 v;
                v.x = acc[ih * 4 + i][jh * 4 + 0];
                v.y = acc[ih * 4 + i][jh * 4 + 1];
                v.z = acc[ih * 4 + i][jh * 4 + 2];
                v.w = acc[ih * 4 + i][jh * 4 + 3];
                *(float4*)(&g_M[(size_t)r * DQ + c]) = v;
            }
        }
}

// ---------------- bf16x6 mma GEMM: C[b][o][t] = sum_k Wc[o][k]*Ht[n][k] + bc[o] ----------------
// Block 128x256, 16 warps (warp 32x64), 3-stage cp.async pipeline, ONE sync per chunk,
// direct-scatter epilogue. mbase selects the weight-row half (0 = theta/phi, 2048 = M).
__global__ __launch_bounds__(512, 1) void k_gemm_mma(int mbase) {
    extern __shared__ __align__(128) char smem[];
    const uint32_t sb = smem_u32(smem);
    const int tid  = threadIdx.x;
    const int wid  = tid >> 5;
    const int lane = tid & 31;
    const int m0 = mbase + blockIdx.x * MT;
    const int n0 = blockIdx.y * NT;
    const int warp_m = (wid & 3) * 32;
    const int warp_n = (wid >> 2) * 64;

    const int frow = tid >> 2;          // 0..127
    const int fgr  = tid & 3;
    const uint32_t soA = sw64(frow, fgr);

    float acc[2][8][4];
#pragma unroll
    for (int i = 0; i < 2; i++)
#pragma unroll
        for (int j = 0; j < 8; j++)
#pragma unroll
            for (int k = 0; k < 4; k++) acc[i][j][k] = 0.f;

    const __nv_bfloat16* Wp[3] = {g_Wp1, g_Wp2, g_Wp3};
    const __nv_bfloat16* Hp[3] = {g_Hp1, g_Hp2, g_Hp3};

    auto issue = [&](int c, int st) {
        const uint32_t base = sb + st * STB;
        const int k0 = c * KC;
        const size_t aoff = (size_t)(m0 + frow) * DQ + k0 + fgr * 8;
        const size_t boff = (size_t)(n0 + frow) * DQ + k0 + fgr * 8;
        const size_t boff2 = boff + (size_t)128 * DQ;
#pragma unroll
        for (int p = 0; p < 3; p++)
            cp16(base + p * APL + soA, Wp[p] + aoff);
#pragma unroll
        for (int p = 0; p < 3; p++) {
            cp16(base + BOFF + p * BPL + soA,        Hp[p] + boff);
            cp16(base + BOFF + p * BPL + soA + 8192, Hp[p] + boff2);
        }
    };

    issue(0, 0); CP_COMMIT();
    issue(1, 1); CP_COMMIT();

    const int lt = lane >> 3;
    const int lr = lane & 7;
    const int aR  = ((lt & 1) << 3) + lr;
    const int aGs = lt >> 1;
    const int bR  = ((lt >> 1) << 3) + lr;
    const int bGs = lt & 1;

    // Single-sync pipeline (stage (c+2)%3 == (c-1)%3 was last read before this
    // iteration's top sync, so the tail issue is safe).
#pragma unroll 1
    for (int c = 0; c < NCH; c++) {
        CP_WAIT1();
        __syncthreads();

        const uint32_t base = sb + (c % STAGES) * STB;

#pragma unroll
        for (int kk = 0; kk < 2; kk++) {
            uint32_t af[3][2][4];
#pragma unroll
            for (int p = 0; p < 3; p++)
#pragma unroll
                for (int mt = 0; mt < 2; mt++)
                    ldm_x4(af[p][mt],
                           base + p * APL + sw64(warp_m + mt * 16 + aR, kk * 2 + aGs));
#pragma unroll
            for (int half = 0; half < 2; half++) {
#pragma unroll
                for (int pb = 0; pb < 3; pb++) {
                    uint32_t bf[2][4];
#pragma unroll
                    for (int qq = 0; qq < 2; qq++)
                        ldm_x4(bf[qq],
                               base + BOFF + pb * BPL +
                               sw64(warp_n + (half * 2 + qq) * 16 + bR, kk * 2 + bGs));
                    const int napr = 3 - pb;
#pragma unroll
                    for (int pa = 0; pa < 3; pa++) {
                        if (pa < napr) {
#pragma unroll
                            for (int mt = 0; mt < 2; mt++)
#pragma unroll
                                for (int nt = 0; nt < 4; nt++) {
                                    const int s = (nt & 1) * 2;
                                    mma16(acc[mt][half * 4 + nt], af[pa][mt],
                                          bf[nt >> 1][s], bf[nt >> 1][s + 1]);
                                }
                        }
                    }
                }
            }
        }

        if (c + 2 < NCH) issue(c + 2, (c + 2) % STAGES);
        CP_COMMIT();
    }

    // direct-scatter epilogue: C[b][o][t] with bias
#pragma unroll
    for (int mt = 0; mt < 2; mt++) {
        const int R0 = m0 + warp_m + mt * 16 + (lane >> 2);
        const float b0v = g_bc[R0];
        const float b1v = g_bc[R0 + 8];
#pragma unroll
        for (int nt = 0; nt < 8; nt++) {
            const int col = n0 + warp_n + nt * 8 + 2 * (lane & 3);
            const int bb = col >> 4;
            const int t  = col & 15;
            float2 v0 = make_float2(acc[mt][nt][0] + b0v, acc[mt][nt][1] + b0v);
            float2 v1 = make_float2(acc[mt][nt][2] + b1v, acc[mt][nt][3] + b1v);
            *(float2*)(&g_C[(size_t)bb * CRW + R0 * 16 + t])       = v0;
            *(float2*)(&g_C[(size_t)bb * CRW + (R0 + 8) * 16 + t]) = v1;
        }
    }
}

// ---------------- scores + softmax (per batch item) ----------------
__global__ __launch_bounds__(256) void k_scores() {
    const int b = blockIdx.x;
    const int tid = threadIdx.x;
    const float* Cb = g_C + (size_t)b * CRW;

    __shared__ float sth[128 * 16];
    __shared__ float sph[128 * 16];
    __shared__ float sS[16][16];

    const int t16 = tid >> 4;
    const int s16 = tid & 15;

    float acc = 0.f;
    for (int o0 = 0; o0 < DHQ; o0 += 128) {
        const float4* srcT = (const float4*)(Cb + o0 * 16);
        const float4* srcP = (const float4*)(Cb + DHQ * 16 + o0 * 16);
        float4* d1 = (float4*)sth;
        float4* d2 = (float4*)sph;
#pragma unroll
        for (int i = tid; i < 512; i += 256) { d1[i] = srcT[i]; d2[i] = srcP[i]; }
        __syncthreads();
#pragma unroll 8
        for (int k = 0; k < 128; k++) acc += sth[k * 16 + t16] * sph[k * 16 + s16];
        __syncthreads();
    }
    sS[t16][s16] = acc * (1.0f / (float)DHQ);
    __syncthreads();

    if (tid < 16) {
        float mx = sS[tid][0];
#pragma unroll
        for (int j = 1; j < 16; j++) mx = fmaxf(mx, sS[tid][j]);
        float e[16], sum = 0.f;
#pragma unroll
        for (int j = 0; j < 16; j++) { e[j] = expf(sS[tid][j] - mx); sum += e[j]; }
        float rs = 1.0f / sum;
#pragma unroll
        for (int j = 0; j < 16; j++) g_alpha[(size_t)b * 256 + tid * 16 + j] = e[j] * rs;
    }
}

// ---------------- residual update: H' = i2*(G alpha^T) + (1+i2)*H + cc ----------------
__global__ __launch_bounds__(256) void k_update() {
    const int dblk = blockIdx.x;        // 0..7 (256 d each)
    const int b    = blockIdx.y;
    const int tid  = threadIdx.x;
    const float* Cb = g_C + (size_t)b * CRW;

    __shared__ float sA[256];
    __shared__ float sg[256][17];

    sA[tid] = g_alpha[(size_t)b * 256 + tid];
#pragma unroll
    for (int i = tid; i < 1024; i += 256) {
        const int r  = i >> 2;
        const int c4 = i & 3;
        float4 v = ((const float4*)(Cb + (size_t)(2048 + dblk * 256 + r) * 16))[c4];
        sg[r][c4 * 4 + 0] = v.x;
        sg[r][c4 * 4 + 1] = v.y;
        sg[r][c4 * 4 + 2] = v.z;
        sg[r][c4 * 4 + 3] = v.w;
    }
    __syncthreads();

    const int tg   = tid >> 6;
    const int dg   = tid & 63;
    const int dloc = dg * 4;
    const int d    = dblk * 256 + dloc;

    float inv4[4], cc4[4], i24[4];
    *(float4*)inv4 = *(const float4*)(&g_inv[d]);
    *(float4*)cc4  = *(const float4*)(&g_cc[d]);
#pragma unroll
    for (int i = 0; i < 4; i++) i24[i] = inv4[i] * inv4[i];

#pragma unroll
    for (int tt = 0; tt < 4; tt++) {
        const int t = tg * 4 + tt;
        const size_t hidx = ((size_t)(b * 16 + t)) * DQ + d;
        float f1[4], f2[4], f3[4];
        load4(&g_Hp1[hidx], f1);
        load4(&g_Hp2[hidx], f2);
        load4(&g_Hp3[hidx], f3);
        uint16_t o1[4], o2[4], o3[4];
#pragma unroll
        for (int i = 0; i < 4; i++) {
            const float h = f1[i] + f2[i] + f3[i];
            float c1 = 0.f;
#pragma unroll
            for (int s = 0; s < 16; s++) c1 += sA[t * 16 + s] * sg[dloc + i][s];
            const float v = i24[i] * c1 + (1.0f + i24[i]) * h + cc4[i];
            bsplit(v, o1[i], o2[i], o3[i]);
        }
        *(uint2*)&g_Hp1[hidx] = make_uint2((uint32_t)o1[0] | ((uint32_t)o1[1] << 16),
                                           (uint32_t)o1[2] | ((uint32_t)o1[3] << 16));
        *(uint2*)&g_Hp2[hidx] = make_uint2((uint32_t)o2[0] | ((uint32_t)o2[1] << 16),
                                           (uint32_t)o2[2] | ((uint32_t)o2[3] << 16));
        *(uint2*)&g_Hp3[hidx] = make_uint2((uint32_t)o3[0] | ((uint32_t)o3[1] << 16),
                                           (uint32_t)o3[2] | ((uint32_t)o3[3] << 16));
    }
}

// ---------------- final: F[b*32768 + t*2048 + d] = relu(BN(h)+x), layout transpose ----------
__global__ __launch_bounds__(256) void k_final(const float* __restrict__ x) {
    __shared__ float s[16][132];
    const int b = blockIdx.x >> 4;
    const int q = blockIdx.x & 15;
    const int tid = threadIdx.x;

    const int tt = tid >> 4;
    const int ug = (tid & 15);
    const size_t base = ((size_t)(b * 16 + tt)) * DQ + q * 128;
#pragma unroll
    for (int r = 0; r < 2; r++) {
        const int uu = ug * 8 + r * 4;
        float f1[4], f2[4], f3[4];
        load4(&g_Hp1[base + uu], f1);
        load4(&g_Hp2[base + uu], f2);
        load4(&g_Hp3[base + uu], f3);
        float4 inv4 = *(const float4*)(&g_inv[q * 128 + uu]);
        float4 ca4  = *(const float4*)(&g_cadd[q * 128 + uu]);
        s[tt][uu + 0] = inv4.x * (f1[0] + f2[0] + f3[0]) + ca4.x;
        s[tt][uu + 1] = inv4.y * (f1[1] + f2[1] + f3[1]) + ca4.y;
        s[tt][uu + 2] = inv4.z * (f1[2] + f2[2] + f3[2]) + ca4.z;
        s[tt][uu + 3] = inv4.w * (f1[3] + f2[3] + f3[3]) + ca4.w;
    }
    __syncthreads();

    const size_t f0 = (size_t)b * DTQ + q * 2048;
    const int o0 = tid * 8;
    float4 xa = *(const float4*)(&x[f0 + o0]);
    float4 xb = *(const float4*)(&x[f0 + o0 + 4]);
    float vo[8];
#pragma unroll
    for (int r = 0; r < 8; r++) {
        const int o = o0 + r;
        vo[r] = s[o & 15][o >> 4];
    }
    float4 va, vb;
    va.x = fmaxf(vo[0] + xa.x, 0.f);
    va.y = fmaxf(vo[1] + xa.y, 0.f);
    va.z = fmaxf(vo[2] + xa.z, 0.f);
    va.w = fmaxf(vo[3] + xa.w, 0.f);
    vb.x = fmaxf(vo[4] + xb.x, 0.f);
    vb.y = fmaxf(vo[5] + xb.y, 0.f);
    vb.z = fmaxf(vo[6] + xb.z, 0.f);
    vb.w = fmaxf(vo[7] + xb.w, 0.f);
    *(float4*)(&g_F[f0 + o0])     = va;
    *(float4*)(&g_F[f0 + o0 + 4]) = vb;
}

// ---------------- fc1 partial: Y1p[ks] = F[:, ksK:(ks+1)K] @ fc1_w[:, ...]^T ----------------
__global__ __launch_bounds__(256) void k_gemm_fc1p(const float* __restrict__ Bw) {
    __shared__ float As[16][132];
    __shared__ float Bs[16][132];
    const int tid = threadIdx.x;
    const int rx  = tid & 15;
    const int ry  = tid >> 4;
    const int row0 = blockIdx.y * 128;
    const int col0 = blockIdx.x * 128;
    const int ks   = blockIdx.z;
    const int kbeg = ks * FC1KC;
    float acc[8][8];
#pragma unroll
    for (int i = 0; i < 8; i++)
#pragma unroll
        for (int j = 0; j < 8; j++) acc[i][j] = 0.f;
    for (int k0 = kbeg; k0 < kbeg + FC1KC; k0 += 16) {
#pragma unroll
        for (int f = tid; f < 512; f += 256) {
            int r = f >> 2, kk = (f & 3) << 2;
            float4 v = *(const float4*)(&g_F[(size_t)(row0 + r) * DTQ + k0 + kk]);
            As[kk + 0][r] = v.x; As[kk + 1][r] = v.y;
            As[kk + 2][r] = v.z; As[kk + 3][r] = v.w;
        }
#pragma unroll
        for (int f = tid; f < 512; f += 256) {
            int cN = f >> 2, kk = (f & 3) << 2;
            float4 v = *(const float4*)(&Bw[(size_t)(col0 + cN) * DTQ + k0 + kk]);
            Bs[kk + 0][cN] = v.x; Bs[kk + 1][cN] = v.y;
            Bs[kk + 2][cN] = v.z; Bs[kk + 3][cN] = v.w;
        }
        __syncthreads();
#pragma unroll
        for (int k = 0; k < 16; k++) {
            float ra[8], rb[8];
            *(float4*)(ra)     = *(const float4*)(&As[k][ry * 4]);
            *(float4*)(ra + 4) = *(const float4*)(&As[k][64 + ry * 4]);
            *(float4*)(rb)     = *(const float4*)(&Bs[k][rx * 4]);
            *(float4*)(rb + 4) = *(const float4*)(&Bs[k][64 + rx * 4]);
#pragma unroll
            for (int i = 0; i < 8; i++)
#pragma unroll
                for (int j = 0; j < 8; j++) acc[i][j] += ra[i] * rb[j];
        }
        __syncthreads();
    }
    float* Yp = g_Y1p[ks];
#pragma unroll
    for (int ih = 0; ih < 2; ih++)
#pragma unroll
        for (int i = 0; i < 4; i++) {
            const int r = row0 + ih * 64 + ry * 4 + i;
#pragma unroll
            for (int jh = 0; jh < 2; jh++) {
                const int c = col0 + jh * 64 + rx * 4;
                float4 v;
                v.x = acc[ih * 4 + i][jh * 4 + 0];
                v.y = acc[ih * 4 + i][jh * 4 + 1];
                v.z = acc[ih * 4 + i][jh * 4 + 2];
                v.w = acc[ih * 4 + i][jh * 4 + 3];
                *(float4*)(&Yp[(size_t)r * 512 + c]) = v;
            }
        }
}

// reduce partials + bias + relu
__global__ void k_fc1red(const float* __restrict__ bias) {
    const size_t i4 = (size_t)blockIdx.x * blockDim.x + threadIdx.x;   // float4 index
    const size_t i  = i4 * 4;
    const int c = (int)(i & 511);
    float4 a = *(const float4*)(&g_Y1p[0][i]);
    float4 b = *(const float4*)(&g_Y1p[1][i]);
    float4 cc = *(const float4*)(&g_Y1p[2][i]);
    float4 d = *(const float4*)(&g_Y1p[3][i]);
    float4 bb = *(const float4*)(&bias[c]);
    float4 v;
    v.x = fmaxf(a.x + b.x + cc.x + d.x + bb.x, 0.f);
    v.y = fmaxf(a.y + b.y + cc.y + d.y + bb.y, 0.f);
    v.z = fmaxf(a.z + b.z + cc.z + d.z + bb.z, 0.f);
    v.w = fmaxf(a.w + b.w + cc.w + d.w + bb.w, 0.f);
    *(float4*)(&g_Y1[i]) = v;
}

// ---------------- fc2 ----------------
__global__ void k_fc2(const float* __restrict__ w, const float* __restrict__ bias,
                      float* __restrict__ out) {
    const int b = blockIdx.x;
    __shared__ float sy[512];
    for (int i = threadIdx.x; i < 512; i += blockDim.x) sy[i] = g_Y1[(size_t)b * 512 + i];
    __syncthreads();
    for (int c = threadIdx.x; c < NCQ; c += blockDim.x) {
        float acc = bias[c];
        const float* wr = w + (size_t)c * 512;
#pragma unroll 8
        for (int n = 0; n < 512; n++) acc += sy[n] * wr[n];
        out[(size_t)b * NCQ + c] = acc;
    }
}

// ---------------- launch ----------------
extern "C" void kernel_launch(void* const* d_in, const int* in_sizes, int n_in,
                              void* d_out, int out_size) {
    const float* x     = (const float*)d_in[0];
    const float* thw   = (const float*)d_in[1];
    const float* phw   = (const float*)d_in[2];
    const float* gw    = (const float*)d_in[3];
    const float* Ww    = (const float*)d_in[4];
    const float* gamma = (const float*)d_in[5];
    const float* beta  = (const float*)d_in[6];
    const float* mean  = (const float*)d_in[7];
    const float* var   = (const float*)d_in[8];
    const float* fc1w  = (const float*)d_in[9];
    const float* fc1b  = (const float*)d_in[10];
    const float* fc2w  = (const float*)d_in[11];
    const float* fc2b  = (const float*)d_in[12];
    float* out = (float*)d_out;

    // lazily created side stream + events (first call is eager, pre-capture)
    static cudaStream_t s1 = nullptr;
    static cudaEvent_t  eA = nullptr, eB = nullptr;
    if (s1 == nullptr) {
        cudaStreamCreateWithFlags(&s1, cudaStreamNonBlocking);
        cudaEventCreateWithFlags(&eA, cudaEventDisableTiming);
        cudaEventCreateWithFlags(&eB, cudaEventDisableTiming);
    }

    cudaFuncSetAttribute(k_gemm_mma, cudaFuncAttributeMaxDynamicSharedMemorySize, SMEMT);

    // launch order arranged so the 4th launch is k_gemm_mma (ncu capture slot)
    k_gemm_M<<<dim3(DQ / 128, DQ / 128), 256>>>(Ww, gw);            // 1
    k_init<<<BQ, 256>>>(x);                                         // 2
    k_foldbias<<<RWS, 256>>>(thw, phw, gamma, beta, mean, var);     // 3

    for (int it = 0; it < TQ; ++it) {
        // theta/phi half (weight rows 0..2047) -> C rows 0..2047
        k_gemm_mma<<<dim3(16, NTOT / NT), 512, SMEMT>>>(0);         // 4 on it==0
        cudaEventRecord(eA, 0);
        cudaStreamWaitEvent(s1, eA, 0);
        k_scores<<<BQ, 256, 0, s1>>>();                             // overlaps G_M
        cudaEventRecord(eB, s1);

        if (it == 0)
            k_bn_prep<<<(DQ + 255) / 256, 256>>>(gamma, beta, mean, var);

        // M half (weight rows 2048..4095) -> C rows 2048..4095
        k_gemm_mma<<<dim3(16, NTOT / NT), 512, SMEMT>>>(2048);

        cudaStreamWaitEvent(0, eB, 0);
        k_update<<<dim3(8, BQ), 256>>>();
    }

    k_final<<<BQ * 16, 256>>>(x);
    k_gemm_fc1p<<<dim3(512 / 128, BQ / 128, FC1KS), 256>>>(fc1w);
    k_fc1red<<<(BQ * 512 / 4) / 256, 256>>>(fc1b);
    k_fc2<<<BQ, 256>>>(fc2w, fc2b, out);
}

// round 16
// speedup vs baseline: 1.0438x; 1.0438x over previous
#include <cuda_runtime.h>
#include <cuda_bf16.h>
#include <math.h>
#include <stdint.h>

// Problem constants
#define BQ   2048
#define TQ   16
#define DQ   2048
#define DHQ  1024
#define NCQ  174
#define DTQ  32768          // D*T
#define RWS  4096           // 2*DH + D  (theta; phi; M rows)
#define NTOT 32768          // B*T columns
#define CRW  65536          // per-batch C stride (4096*16)

// GEMM tiling
#define MT     128
#define NT     256
#define KC     32
#define NCH    (DQ / KC)    // 64
#define STAGES 3
#define APL    8192                    // A plane tile: 128 rows * 64B
#define BPL    16384                   // B plane tile: 256 rows * 64B
#define BOFF   (3 * APL)               // 24576
#define STB    (3 * APL + 3 * BPL)     // 73728
#define SMEMT  (STAGES * STB)          // 221184

// fc1 (bf16x4 mma, split-K)
#define FC1KS   4
#define F1KC    (DTQ / FC1KS)          // 8192 K per split
#define F1NCH   (F1KC / KC)            // 256 chunks
#define F1TPL   8192                   // 128 rows * 64B per plane tile
#define F1STB   (4 * F1TPL)            // 32768 (Ap1,Ap2,Bp1,Bp2)
#define F1SMEM  (3 * F1STB)            // 98304

// ---------------- device scratch ----------------
__device__ float g_inv [DQ];
__device__ float g_cadd[DQ];
__device__ float g_cc  [DQ];
__device__ float g_M   [(size_t)DQ * DQ];       // W_w @ g_w
__device__ float g_bc  [RWS];
__device__ float g_alpha[(size_t)BQ * 256];     // softmax alpha per batch [t][s]
__device__ __nv_bfloat16 g_Wp1[(size_t)RWS * DQ];   // folded weight planes
__device__ __nv_bfloat16 g_Wp2[(size_t)RWS * DQ];
__device__ __nv_bfloat16 g_Wp3[(size_t)RWS * DQ];
__device__ __nv_bfloat16 g_Hp1[(size_t)NTOT * DQ];  // h planes [n=b*16+t][k=d]
__device__ __nv_bfloat16 g_Hp2[(size_t)NTOT * DQ];
__device__ __nv_bfloat16 g_Hp3[(size_t)NTOT * DQ];
__device__ float g_C   [(size_t)BQ * CRW];      // projections [b][o][t]
__device__ __nv_bfloat16 g_Fp1[(size_t)BQ * DTQ];   // F planes (fc1 A operand)
__device__ __nv_bfloat16 g_Fp2[(size_t)BQ * DTQ];
__device__ __nv_bfloat16 g_W1a[(size_t)512 * DTQ];  // fc1 weight planes
__device__ __nv_bfloat16 g_W1b[(size_t)512 * DTQ];
__device__ float g_Y1  [(size_t)BQ * 512];
__device__ float g_Y1p [FC1KS][(size_t)BQ * 512];   // fc1 K-split partials

// ---------------- helpers ----------------
__device__ __forceinline__ uint32_t smem_u32(const void* p) {
    uint32_t a;
    asm("{ .reg .u64 t; cvta.to.shared.u64 t, %1; cvt.u32.u64 %0, t; }" : "=r"(a) : "l"(p));
    return a;
}

__device__ __forceinline__ void cp16(uint32_t dst, const void* src) {
    asm volatile("cp.async.cg.shared.global [%0], [%1], 16;" :: "r"(dst), "l"(src));
}
#define CP_COMMIT() asm volatile("cp.async.commit_group;" ::: "memory")
#define CP_WAIT1()  asm volatile("cp.async.wait_group 1;" ::: "memory")
#define CP_WAIT0()  asm volatile("cp.async.wait_group 0;" ::: "memory")

__device__ __forceinline__ void ldm_x4(uint32_t* r, uint32_t addr) {
    asm volatile("ldmatrix.sync.aligned.m8n8.x4.shared.b16 {%0,%1,%2,%3}, [%4];"
                 : "=r"(r[0]), "=r"(r[1]), "=r"(r[2]), "=r"(r[3]) : "r"(addr));
}

__device__ __forceinline__ void mma16(float* c, const uint32_t* a, uint32_t b0, uint32_t b1) {
    asm volatile("mma.sync.aligned.m16n8k16.row.col.f32.bf16.bf16.f32 "
                 "{%0,%1,%2,%3},{%4,%5,%6,%7},{%8,%9},{%0,%1,%2,%3};"
                 : "+f"(c[0]), "+f"(c[1]), "+f"(c[2]), "+f"(c[3])
                 : "r"(a[0]), "r"(a[1]), "r"(a[2]), "r"(a[3]), "r"(b0), "r"(b1));
}

// 3-way bf16 split: v ~= b1 + b2 + b3
__device__ __forceinline__ void bsplit(float v, uint16_t& o1, uint16_t& o2, uint16_t& o3) {
    __nv_bfloat16 x1 = __float2bfloat16_rn(v);
    float r1 = v - __bfloat162float(x1);
    __nv_bfloat16 x2 = __float2bfloat16_rn(r1);
    float r2 = r1 - __bfloat162float(x2);
    __nv_bfloat16 x3 = __float2bfloat16_rn(r2);
    o1 = *(uint16_t*)&x1;
    o2 = *(uint16_t*)&x2;
    o3 = *(uint16_t*)&x3;
}

// 2-way bf16 split
__device__ __forceinline__ void bsplit2(float v, uint16_t& o1, uint16_t& o2) {
    __nv_bfloat16 x1 = __float2bfloat16_rn(v);
    float r1 = v - __bfloat162float(x1);
    __nv_bfloat16 x2 = __float2bfloat16_rn(r1);
    o1 = *(uint16_t*)&x1;
    o2 = *(uint16_t*)&x2;
}

__device__ __forceinline__ float bf2f(uint16_t u) {
    __nv_bfloat16 h = *(__nv_bfloat16*)&u;
    return __bfloat162float(h);
}

__device__ __forceinline__ void load4(const __nv_bfloat16* p, float* f) {
    uint2 u = *(const uint2*)p;
    const uint16_t* h = (const uint16_t*)&u;
    f[0] = bf2f(h[0]); f[1] = bf2f(h[1]); f[2] = bf2f(h[2]); f[3] = bf2f(h[3]);
}

// 64B-row XOR swizzle: conflict-free for 8-row ldmatrix and 16B fills
__device__ __forceinline__ uint32_t sw64(int row, int g) {
    return (uint32_t)(row * 64 + ((g ^ ((row >> 1) & 3)) << 4));
}

// ---------------- prep kernels ----------------
__global__ void k_bn_prep(const float* __restrict__ gamma, const float* __restrict__ beta,
                          const float* __restrict__ mean,  const float* __restrict__ var) {
    int d = blockIdx.x * blockDim.x + threadIdx.x;
    if (d < DQ) {
        float inv = gamma[d] * rsqrtf(var[d] + 1e-5f);
        float ca  = beta[d] - mean[d] * inv;
        g_inv[d]  = inv;
        g_cadd[d] = ca;
        g_cc[d]   = ca * (2.0f * inv + 1.0f);
    }
}

__global__ __launch_bounds__(256) void k_foldbias(
    const float* __restrict__ thw, const float* __restrict__ phw,
    const float* __restrict__ gamma, const float* __restrict__ beta,
    const float* __restrict__ mean,  const float* __restrict__ var) {
    const int o = blockIdx.x;
    const int tid = threadIdx.x;
    const float* row;
    if (o < 1024)      row = thw + (size_t)o * DQ;
    else if (o < 2048) row = phw + (size_t)(o - 1024) * DQ;
    else               row = g_M + (size_t)(o - 2048) * DQ;
    float accb = 0.f;
    for (int d = tid; d < DQ; d += 256) {
        float inv = gamma[d] * rsqrtf(var[d] + 1e-5f);
        float ca  = beta[d] - mean[d] * inv;
        float w   = row[d];
        float v   = w * inv;
        uint16_t b1, b2, b3;
        bsplit(v, b1, b2, b3);
        size_t idx = (size_t)o * DQ + d;
        *(uint16_t*)&g_Wp1[idx] = b1;
        *(uint16_t*)&g_Wp2[idx] = b2;
        *(uint16_t*)&g_Wp3[idx] = b3;
        accb += w * ca;
    }
    __shared__ float red[256];
    red[tid] = accb;
    __syncthreads();
    for (int st = 128; st > 0; st >>= 1) {
        if (tid < st) red[tid] += red[tid + st];
        __syncthreads();
    }
    if (tid == 0) g_bc[o] = red[0];
}

// Ht planes[n=b*16+t][k=d] = split(x[b*32768 + d*16 + t])
__global__ __launch_bounds__(256) void k_init(const float* __restrict__ x) {
    __shared__ float s[128 * 17];
    int b = blockIdx.x, tid = threadIdx.x;
    for (int d0 = 0; d0 < DQ; d0 += 128) {
        for (int i = tid; i < 2048; i += 256) {
            int dd = i >> 4, t = i & 15;
            s[dd * 17 + t] = x[(size_t)b * DTQ + d0 * 16 + i];
        }
        __syncthreads();
        int t = tid >> 4, j = tid & 15;
        size_t base = ((size_t)(b * 16 + t)) * DQ + d0 + j * 8;
#pragma unroll
        for (int i = 0; i < 8; i += 2) {
            float v0 = s[(j * 8 + i) * 17 + t];
            float v1 = s[(j * 8 + i + 1) * 17 + t];
            uint16_t a1, a2, a3, c1, c2, c3;
            bsplit(v0, a1, a2, a3);
            bsplit(v1, c1, c2, c3);
            *(uint32_t*)&g_Hp1[base + i] = (uint32_t)a1 | ((uint32_t)c1 << 16);
            *(uint32_t*)&g_Hp2[base + i] = (uint32_t)a2 | ((uint32_t)c2 << 16);
            *(uint32_t*)&g_Hp3[base + i] = (uint32_t)a3 | ((uint32_t)c3 << 16);
        }
        __syncthreads();
    }
}

// fc1 weight split into 2 bf16 planes
__global__ __launch_bounds__(256) void k_fc1split(const float* __restrict__ w) {
    const int r = blockIdx.x;
    for (int k = threadIdx.x; k < DTQ; k += 256) {
        float v = w[(size_t)r * DTQ + k];
        uint16_t b1, b2;
        bsplit2(v, b1, b2);
        *(uint16_t*)&g_W1a[(size_t)r * DTQ + k] = b1;
        *(uint16_t*)&g_W1b[(size_t)r * DTQ + k] = b2;
    }
}

// ---------------- M = W_w @ g_w (fp32 SIMT, run once) ----------------
__global__ __launch_bounds__(256) void k_gemm_M(const float* __restrict__ A,
                                                const float* __restrict__ B) {
    __shared__ float As[16][132];
    __shared__ float Bs[16][132];
    const int tid = threadIdx.x;
    const int rx  = tid & 15;
    const int ry  = tid >> 4;
    const int row0 = blockIdx.y * 128;
    const int col0 = blockIdx.x * 128;
    float acc[8][8];
#pragma unroll
    for (int i = 0; i < 8; i++)
#pragma unroll
        for (int j = 0; j < 8; j++) acc[i][j] = 0.f;
    for (int k0 = 0; k0 < DHQ; k0 += 16) {
#pragma unroll
        for (int f = tid; f < 512; f += 256) {
            int r = f >> 2, kk = (f & 3) << 2;
            float4 v = *(const float4*)(&A[(size_t)(row0 + r) * DHQ + k0 + kk]);
            As[kk + 0][r] = v.x; As[kk + 1][r] = v.y;
            As[kk + 2][r] = v.z; As[kk + 3][r] = v.w;
        }
#pragma unroll
        for (int f = tid; f < 512; f += 256) {
            int k = f >> 5, cc = (f & 31) << 2;
            float4 v = *(const float4*)(&B[(size_t)(k0 + k) * DQ + col0 + cc]);
            *(float4*)(&Bs[k][cc]) = v;
        }
        __syncthreads();
#pragma unroll
        for (int k = 0; k < 16; k++) {
            float ra[8], rb[8];
            *(float4*)(ra)     = *(const float4*)(&As[k][ry * 4]);
            *(float4*)(ra + 4) = *(const float4*)(&As[k][64 + ry * 4]);
            *(float4*)(rb)     = *(const float4*)(&Bs[k][rx * 4]);
            *(float4*)(rb + 4) = *(const float4*)(&Bs[k][64 + rx * 4]);
#pragma unroll
            for (int i = 0; i < 8; i++)
#pragma unroll
                for (int j = 0; j < 8; j++) acc[i][j] += ra[i] * rb[j];
        }
        __syncthreads();
    }
#pragma unroll
    for (int ih = 0; ih < 2; ih++)
#pragma unroll
        for (int i = 0; i < 4; i++) {
            const int r = row0 + ih * 64 + ry * 4 + i;
#pragma unroll
            for (int jh = 0; jh < 2; jh++) {
                const int c = col0 + jh * 64 + rx * 4;
                float4 v;
                v.x = acc[ih * 4 + i][jh * 4 + 0];
                v.y = acc[ih * 4 + i][jh * 4 + 1];
                v.z = acc[ih * 4 + i][jh * 4 + 2];
                v.w = acc[ih * 4 + i][jh * 4 + 3];
                *(float4*)(&g_M[(size_t)r * DQ + c]) = v;
            }
        }
}

// ---------------- bf16x6 mma GEMM: C[b][o][t] = sum_k Wc[o][k]*Ht[n][k] + bc[o] ----------------
// Block 128x256, 16 warps (warp 32x64), 3-stage cp.async pipeline, ONE sync per chunk,
// direct-scatter epilogue. (round-14 verified fastest configuration)
__global__ __launch_bounds__(512, 1) void k_gemm_mma() {
    extern __shared__ __align__(128) char smem[];
    const uint32_t sb = smem_u32(smem);
    const int tid  = threadIdx.x;
    const int wid  = tid >> 5;
    const int lane = tid & 31;
    const int m0 = blockIdx.x * MT;
    const int n0 = blockIdx.y * NT;
    const int warp_m = (wid & 3) * 32;
    const int warp_n = (wid >> 2) * 64;

    const int frow = tid >> 2;          // 0..127
    const int fgr  = tid & 3;
    const uint32_t soA = sw64(frow, fgr);

    float acc[2][8][4];
#pragma unroll
    for (int i = 0; i < 2; i++)
#pragma unroll
        for (int j = 0; j < 8; j++)
#pragma unroll
            for (int k = 0; k < 4; k++) acc[i][j][k] = 0.f;

    const __nv_bfloat16* Wp[3] = {g_Wp1, g_Wp2, g_Wp3};
    const __nv_bfloat16* Hp[3] = {g_Hp1, g_Hp2, g_Hp3};

    auto issue = [&](int c, int st) {
        const uint32_t base = sb + st * STB;
        const int k0 = c * KC;
        const size_t aoff = (size_t)(m0 + frow) * DQ + k0 + fgr * 8;
        const size_t boff = (size_t)(n0 + frow) * DQ + k0 + fgr * 8;
        const size_t boff2 = boff + (size_t)128 * DQ;
#pragma unroll
        for (int p = 0; p < 3; p++)
            cp16(base + p * APL + soA, Wp[p] + aoff);
#pragma unroll
        for (int p = 0; p < 3; p++) {
            cp16(base + BOFF + p * BPL + soA,        Hp[p] + boff);
            cp16(base + BOFF + p * BPL + soA + 8192, Hp[p] + boff2);
        }
    };

    issue(0, 0); CP_COMMIT();
    issue(1, 1); CP_COMMIT();

    const int lt = lane >> 3;
    const int lr = lane & 7;
    const int aR  = ((lt & 1) << 3) + lr;
    const int aGs = lt >> 1;
    const int bR  = ((lt >> 1) << 3) + lr;
    const int bGs = lt & 1;

#pragma unroll 1
    for (int c = 0; c < NCH; c++) {
        CP_WAIT1();
        __syncthreads();

        const uint32_t base = sb + (c % STAGES) * STB;

#pragma unroll
        for (int kk = 0; kk < 2; kk++) {
            uint32_t af[3][2][4];
#pragma unroll
            for (int p = 0; p < 3; p++)
#pragma unroll
                for (int mt = 0; mt < 2; mt++)
                    ldm_x4(af[p][mt],
                           base + p * APL + sw64(warp_m + mt * 16 + aR, kk * 2 + aGs));
#pragma unroll
            for (int half = 0; half < 2; half++) {
#pragma unroll
                for (int pb = 0; pb < 3; pb++) {
                    uint32_t bf[2][4];
#pragma unroll
                    for (int qq = 0; qq < 2; qq++)
                        ldm_x4(bf[qq],
                               base + BOFF + pb * BPL +
                               sw64(warp_n + (half * 2 + qq) * 16 + bR, kk * 2 + bGs));
                    const int napr = 3 - pb;
#pragma unroll
                    for (int pa = 0; pa < 3; pa++) {
                        if (pa < napr) {
#pragma unroll
                            for (int mt = 0; mt < 2; mt++)
#pragma unroll
                                for (int nt = 0; nt < 4; nt++) {
                                    const int s = (nt & 1) * 2;
                                    mma16(acc[mt][half * 4 + nt], af[pa][mt],
                                          bf[nt >> 1][s], bf[nt >> 1][s + 1]);
                                }
                        }
                    }
                }
            }
        }

        if (c + 2 < NCH) issue(c + 2, (c + 2) % STAGES);
        CP_COMMIT();
    }

    // direct-scatter epilogue: C[b][o][t] with bias
#pragma unroll
    for (int mt = 0; mt < 2; mt++) {
        const int R0 = m0 + warp_m + mt * 16 + (lane >> 2);
        const float b0v = g_bc[R0];
        const float b1v = g_bc[R0 + 8];
#pragma unroll
        for (int nt = 0; nt < 8; nt++) {
            const int col = n0 + warp_n + nt * 8 + 2 * (lane & 3);
            const int bb = col >> 4;
            const int t  = col & 15;
            float2 v0 = make_float2(acc[mt][nt][0] + b0v, acc[mt][nt][1] + b0v);
            float2 v1 = make_float2(acc[mt][nt][2] + b1v, acc[mt][nt][3] + b1v);
            *(float2*)(&g_C[(size_t)bb * CRW + R0 * 16 + t])       = v0;
            *(float2*)(&g_C[(size_t)bb * CRW + (R0 + 8) * 16 + t]) = v1;
        }
    }
}

// ---------------- scores + softmax (per batch item), double-buffered cp.async ----------------
__global__ __launch_bounds__(256) void k_scores() {
    const int b = blockIdx.x;
    const int tid = threadIdx.x;
    const float* Cb = g_C + (size_t)b * CRW;

    __shared__ float sth[2][2048];
    __shared__ float sph[2][2048];
    __shared__ float sS[16][16];
    const uint32_t a_th = smem_u32(sth);
    const uint32_t a_ph = smem_u32(sph);

    const int t16 = tid >> 4;
    const int s16 = tid & 15;
    const int g0 = tid * 2;   // two 16B granules per thread per tile

    auto issueS = [&](int c) {
        const int buf = c & 1;
        const float* srcT = Cb + c * 2048;
        const float* srcP = Cb + DHQ * 16 + c * 2048;
        cp16(a_th + buf * 8192 + g0 * 16,      srcT + g0 * 4);
        cp16(a_th + buf * 8192 + g0 * 16 + 16, srcT + g0 * 4 + 4);
        cp16(a_ph + buf * 8192 + g0 * 16,      srcP + g0 * 4);
        cp16(a_ph + buf * 8192 + g0 * 16 + 16, srcP + g0 * 4 + 4);
    };

    issueS(0); CP_COMMIT();

    float acc = 0.f;
    for (int c = 0; c < 8; c++) {
        CP_WAIT0();
        __syncthreads();
        if (c + 1 < 8) { issueS(c + 1); CP_COMMIT(); }
        const int buf = c & 1;
#pragma unroll 8
        for (int k = 0; k < 128; k++)
            acc += sth[buf][k * 16 + t16] * sph[buf][k * 16 + s16];
    }
    __syncthreads();
    sS[t16][s16] = acc * (1.0f / (float)DHQ);
    __syncthreads();

    if (tid < 16) {
        float mx = sS[tid][0];
#pragma unroll
        for (int j = 1; j < 16; j++) mx = fmaxf(mx, sS[tid][j]);
        float e[16], sum = 0.f;
#pragma unroll
        for (int j = 0; j < 16; j++) { e[j] = expf(sS[tid][j] - mx); sum += e[j]; }
        float rs = 1.0f / sum;
#pragma unroll
        for (int j = 0; j < 16; j++) g_alpha[(size_t)b * 256 + tid * 16 + j] = e[j] * rs;
    }
}

// ---------------- residual update: H' = i2*(G alpha^T) + (1+i2)*H + cc ----------------
__global__ __launch_bounds__(256) void k_update() {
    const int dblk = blockIdx.x;        // 0..7 (256 d each)
    const int b    = blockIdx.y;
    const int tid  = threadIdx.x;
    const float* Cb = g_C + (size_t)b * CRW;

    __shared__ float sA[256];
    __shared__ float sg[256][17];

    sA[tid] = g_alpha[(size_t)b * 256 + tid];
#pragma unroll
    for (int i = tid; i < 1024; i += 256) {
        const int r  = i >> 2;
        const int c4 = i & 3;
        float4 v = ((const float4*)(Cb + (size_t)(2048 + dblk * 256 + r) * 16))[c4];
        sg[r][c4 * 4 + 0] = v.x;
        sg[r][c4 * 4 + 1] = v.y;
        sg[r][c4 * 4 + 2] = v.z;
        sg[r][c4 * 4 + 3] = v.w;
    }
    __syncthreads();

    const int tg   = tid >> 6;
    const int dg   = tid & 63;
    const int dloc = dg * 4;
    const int d    = dblk * 256 + dloc;

    float inv4[4], cc4[4], i24[4];
    *(float4*)inv4 = *(const float4*)(&g_inv[d]);
    *(float4*)cc4  = *(const float4*)(&g_cc[d]);
#pragma unroll
    for (int i = 0; i < 4; i++) i24[i] = inv4[i] * inv4[i];

#pragma unroll
    for (int tt = 0; tt < 4; tt++) {
        const int t = tg * 4 + tt;
        const size_t hidx = ((size_t)(b * 16 + t)) * DQ + d;
        float f1[4], f2[4], f3[4];
        load4(&g_Hp1[hidx], f1);
        load4(&g_Hp2[hidx], f2);
        load4(&g_Hp3[hidx], f3);
        uint16_t o1[4], o2[4], o3[4];
#pragma unroll
        for (int i = 0; i < 4; i++) {
            const float h = f1[i] + f2[i] + f3[i];
            float c1 = 0.f;
#pragma unroll
            for (int s = 0; s < 16; s++) c1 += sA[t * 16 + s] * sg[dloc + i][s];
            const float v = i24[i] * c1 + (1.0f + i24[i]) * h + cc4[i];
            bsplit(v, o1[i], o2[i], o3[i]);
        }
        *(uint2*)&g_Hp1[hidx] = make_uint2((uint32_t)o1[0] | ((uint32_t)o1[1] << 16),
                                           (uint32_t)o1[2] | ((uint32_t)o1[3] << 16));
        *(uint2*)&g_Hp2[hidx] = make_uint2((uint32_t)o2[0] | ((uint32_t)o2[1] << 16),
                                           (uint32_t)o2[2] | ((uint32_t)o2[3] << 16));
        *(uint2*)&g_Hp3[hidx] = make_uint2((uint32_t)o3[0] | ((uint32_t)o3[1] << 16),
                                           (uint32_t)o3[2] | ((uint32_t)o3[3] << 16));
    }
}

// ---------------- final: Fp = split2(relu(BN(h)+x)), layout transpose ----------
__global__ __launch_bounds__(256) void k_final(const float* __restrict__ x) {
    __shared__ float s[16][132];
    const int b = blockIdx.x >> 4;
    const int q = blockIdx.x & 15;
    const int tid = threadIdx.x;

    const int tt = tid >> 4;
    const int ug = (tid & 15);
    const size_t base = ((size_t)(b * 16 + tt)) * DQ + q * 128;
#pragma unroll
    for (int r = 0; r < 2; r++) {
        const int uu = ug * 8 + r * 4;
        float f1[4], f2[4], f3[4];
        load4(&g_Hp1[base + uu], f1);
        load4(&g_Hp2[base + uu], f2);
        load4(&g_Hp3[base + uu], f3);
        float4 inv4 = *(const float4*)(&g_inv[q * 128 + uu]);
        float4 ca4  = *(const float4*)(&g_cadd[q * 128 + uu]);
        s[tt][uu + 0] = inv4.x * (f1[0] + f2[0] + f3[0]) + ca4.x;
        s[tt][uu + 1] = inv4.y * (f1[1] + f2[1] + f3[1]) + ca4.y;
        s[tt][uu + 2] = inv4.z * (f1[2] + f2[2] + f3[2]) + ca4.z;
        s[tt][uu + 3] = inv4.w * (f1[3] + f2[3] + f3[3]) + ca4.w;
    }
    __syncthreads();

    const size_t f0 = (size_t)b * DTQ + q * 2048;
    const int o0 = tid * 8;
    float4 xa = *(const float4*)(&x[f0 + o0]);
    float4 xb = *(const float4*)(&x[f0 + o0 + 4]);
    float vo[8];
#pragma unroll
    for (int r = 0; r < 8; r++) {
        const int o = o0 + r;
        vo[r] = s[o & 15][o >> 4];
    }
    const float xr[8] = {xa.x, xa.y, xa.z, xa.w, xb.x, xb.y, xb.z, xb.w};
    uint16_t p1[8], p2[8];
#pragma unroll
    for (int r = 0; r < 8; r++) {
        float v = fmaxf(vo[r] + xr[r], 0.f);
        bsplit2(v, p1[r], p2[r]);
    }
    *(uint2*)&g_Fp1[f0 + o0]     = make_uint2((uint32_t)p1[0] | ((uint32_t)p1[1] << 16),
                                              (uint32_t)p1[2] | ((uint32_t)p1[3] << 16));
    *(uint2*)&g_Fp1[f0 + o0 + 4] = make_uint2((uint32_t)p1[4] | ((uint32_t)p1[5] << 16),
                                              (uint32_t)p1[6] | ((uint32_t)p1[7] << 16));
    *(uint2*)&g_Fp2[f0 + o0]     = make_uint2((uint32_t)p2[0] | ((uint32_t)p2[1] << 16),
                                              (uint32_t)p2[2] | ((uint32_t)p2[3] << 16));
    *(uint2*)&g_Fp2[f0 + o0 + 4] = make_uint2((uint32_t)p2[4] | ((uint32_t)p2[5] << 16),
                                              (uint32_t)p2[6] | ((uint32_t)p2[7] << 16));
}

// ---------------- fc1 bf16x4 mma partials: Y1p[ks] = F @ fc1_w^T (K slice) ----------------
// Block 128x128, 8 warps (warp 32x64), 3-stage cp.async pipeline, 2 planes each side,
// 3 products (11,21,12).
__global__ __launch_bounds__(256, 1) void k_fc1mma() {
    extern __shared__ __align__(128) char smem[];
    const uint32_t sb = smem_u32(smem);
    const int tid  = threadIdx.x;
    const int wid  = tid >> 5;
    const int lane = tid & 31;
    const int n0 = blockIdx.x * 128;
    const int m0 = blockIdx.y * 128;
    const int ks = blockIdx.z;
    const int kbeg = ks * F1KC;
    const int warp_m = (wid & 3) * 32;
    const int warp_n = (wid >> 2) * 64;

    const int frow = tid >> 1;          // 0..127
    const int fg   = (tid & 1) * 2;     // granules fg, fg+1

    float acc[2][8][4];
#pragma unroll
    for (int i = 0; i < 2; i++)
#pragma unroll
        for (int j = 0; j < 8; j++)
#pragma unroll
            for (int k = 0; k < 4; k++) acc[i][j][k] = 0.f;

    const __nv_bfloat16* Ap[2] = {g_Fp1, g_Fp2};
    const __nv_bfloat16* Bp[2] = {g_W1a, g_W1b};

    auto issue = [&](int c, int st) {
        const uint32_t base = sb + st * F1STB;
        const int k0 = kbeg + c * KC;
        const size_t aoff = (size_t)(m0 + frow) * DTQ + k0 + fg * 8;
        const size_t boff = (size_t)(n0 + frow) * DTQ + k0 + fg * 8;
        const uint32_t so0 = sw64(frow, fg);
        const uint32_t so1 = sw64(frow, fg + 1);
#pragma unroll
        for (int p = 0; p < 2; p++) {
            cp16(base + p * F1TPL + so0, Ap[p] + aoff);
            cp16(base + p * F1TPL + so1, Ap[p] + aoff + 8);
            cp16(base + (2 + p) * F1TPL + so0, Bp[p] + boff);
            cp16(base + (2 + p) * F1TPL + so1, Bp[p] + boff + 8);
        }
    };

    issue(0, 0); CP_COMMIT();
    issue(1, 1); CP_COMMIT();

    const int lt = lane >> 3;
    const int lr = lane & 7;
    const int aR  = ((lt & 1) << 3) + lr;
    const int aGs = lt >> 1;
    const int bR  = ((lt >> 1) << 3) + lr;
    const int bGs = lt & 1;

#pragma unroll 1
    for (int c = 0; c < F1NCH; c++) {
        CP_WAIT1();
        __syncthreads();

        const uint32_t base = sb + (c % 3) * F1STB;

#pragma unroll
        for (int kk = 0; kk < 2; kk++) {
            uint32_t af[2][2][4];
#pragma unroll
            for (int p = 0; p < 2; p++)
#pragma unroll
                for (int mt = 0; mt < 2; mt++)
                    ldm_x4(af[p][mt],
                           base + p * F1TPL + sw64(warp_m + mt * 16 + aR, kk * 2 + aGs));
            uint32_t bfr[2][4][4];
#pragma unroll
            for (int p = 0; p < 2; p++)
#pragma unroll
                for (int q = 0; q < 4; q++)
                    ldm_x4(bfr[p][q],
                           base + (2 + p) * F1TPL +
                           sw64(warp_n + q * 16 + bR, kk * 2 + bGs));
#pragma unroll
            for (int mt = 0; mt < 2; mt++)
#pragma unroll
                for (int nt = 0; nt < 8; nt++) {
                    const int pq = nt >> 1;
                    const int s  = (nt & 1) * 2;
                    float* C = acc[mt][nt];
                    mma16(C, af[1][mt], bfr[0][pq][s], bfr[0][pq][s + 1]);   // A2B1
                    mma16(C, af[0][mt], bfr[1][pq][s], bfr[1][pq][s + 1]);   // A1B2
                    mma16(C, af[0][mt], bfr[0][pq][s], bfr[0][pq][s + 1]);   // A1B1
                }
        }

        if (c + 2 < F1NCH) issue(c + 2, (c + 2) % 3);
        CP_COMMIT();
    }

    float* Yp = g_Y1p[ks];
#pragma unroll
    for (int mt = 0; mt < 2; mt++) {
        const int R0 = m0 + warp_m + mt * 16 + (lane >> 2);
#pragma unroll
        for (int nt = 0; nt < 8; nt++) {
            const int col = n0 + warp_n + nt * 8 + 2 * (lane & 3);
            *(float2*)(&Yp[(size_t)R0 * 512 + col]) =
                make_float2(acc[mt][nt][0], acc[mt][nt][1]);
            *(float2*)(&Yp[(size_t)(R0 + 8) * 512 + col]) =
                make_float2(acc[mt][nt][2], acc[mt][nt][3]);
        }
    }
}

// reduce partials + bias + relu
__global__ void k_fc1red(const float* __restrict__ bias) {
    const size_t i4 = (size_t)blockIdx.x * blockDim.x + threadIdx.x;
    const size_t i  = i4 * 4;
    const int c = (int)(i & 511);
    float4 a = *(const float4*)(&g_Y1p[0][i]);
    float4 b = *(const float4*)(&g_Y1p[1][i]);
    float4 cc = *(const float4*)(&g_Y1p[2][i]);
    float4 d = *(const float4*)(&g_Y1p[3][i]);
    float4 bb = *(const float4*)(&bias[c]);
    float4 v;
    v.x = fmaxf(a.x + b.x + cc.x + d.x + bb.x, 0.f);
    v.y = fmaxf(a.y + b.y + cc.y + d.y + bb.y, 0.f);
    v.z = fmaxf(a.z + b.z + cc.z + d.z + bb.z, 0.f);
    v.w = fmaxf(a.w + b.w + cc.w + d.w + bb.w, 0.f);
    *(float4*)(&g_Y1[i]) = v;
}

// ---------------- fc2 ----------------
__global__ void k_fc2(const float* __restrict__ w, const float* __restrict__ bias,
                      float* __restrict__ out) {
    const int b = blockIdx.x;
    __shared__ float sy[512];
    for (int i = threadIdx.x; i < 512; i += blockDim.x) sy[i] = g_Y1[(size_t)b * 512 + i];
    __syncthreads();
    for (int c = threadIdx.x; c < NCQ; c += blockDim.x) {
        float acc = bias[c];
        const float* wr = w + (size_t)c * 512;
#pragma unroll 8
        for (int n = 0; n < 512; n++) acc += sy[n] * wr[n];
        out[(size_t)b * NCQ + c] = acc;
    }
}

// ---------------- launch ----------------
extern "C" void kernel_launch(void* const* d_in, const int* in_sizes, int n_in,
                              void* d_out, int out_size) {
    const float* x     = (const float*)d_in[0];
    const float* thw   = (const float*)d_in[1];
    const float* phw   = (const float*)d_in[2];
    const float* gw    = (const float*)d_in[3];
    const float* Ww    = (const float*)d_in[4];
    const float* gamma = (const float*)d_in[5];
    const float* beta  = (const float*)d_in[6];
    const float* mean  = (const float*)d_in[7];
    const float* var   = (const float*)d_in[8];
    const float* fc1w  = (const float*)d_in[9];
    const float* fc1b  = (const float*)d_in[10];
    const float* fc2w  = (const float*)d_in[11];
    const float* fc2b  = (const float*)d_in[12];
    float* out = (float*)d_out;

    cudaFuncSetAttribute(k_gemm_mma, cudaFuncAttributeMaxDynamicSharedMemorySize, SMEMT);
    cudaFuncSetAttribute(k_fc1mma, cudaFuncAttributeMaxDynamicSharedMemorySize, F1SMEM);

    // launch order arranged so the 4th launch is k_gemm_mma (ncu capture slot)
    k_gemm_M<<<dim3(DQ / 128, DQ / 128), 256>>>(Ww, gw);            // 1
    k_init<<<BQ, 256>>>(x);                                         // 2
    k_foldbias<<<RWS, 256>>>(thw, phw, gamma, beta, mean, var);     // 3
    k_gemm_mma<<<dim3(RWS / MT, NTOT / NT), 512, SMEMT>>>();        // 4 <- profile
    k_bn_prep<<<(DQ + 255) / 256, 256>>>(gamma, beta, mean, var);   // 5
    k_scores<<<BQ, 256>>>();                                        // 6
    k_update<<<dim3(8, BQ), 256>>>();                               // 7

    for (int it = 1; it < TQ; ++it) {
        k_gemm_mma<<<dim3(RWS / MT, NTOT / NT), 512, SMEMT>>>();
        k_scores<<<BQ, 256>>>();
        k_update<<<dim3(8, BQ), 256>>>();
    }

    k_fc1split<<<512, 256>>>(fc1w);
    k_final<<<BQ * 16, 256>>>(x);
    k_fc1mma<<<dim3(4, BQ / 128, FC1KS), 256, F1SMEM>>>();
    k_fc1red<<<(BQ * 512 / 4) / 256, 256>>>(fc1b);
    k_fc2<<<BQ, 256>>>(fc2w, fc2b, out);
}

// round 17
// speedup vs baseline: 1.0445x; 1.0006x over previous
#include <cuda_runtime.h>
#include <cuda_bf16.h>
#include <math.h>
#include <stdint.h>

// Problem constants
#define BQ   2048
#define TQ   16
#define DQ   2048
#define DHQ  1024
#define NCQ  174
#define DTQ  32768          // D*T
#define RWS  4096           // 2*DH + D  (theta; phi; M rows)
#define NTOT 32768          // B*T columns
#define CRW  65536          // per-batch C stride (4096*16)

// GEMM tiling
#define MT     128
#define NT     256
#define KC     32
#define NCH    (DQ / KC)    // 64
#define STAGES 3
#define APL    8192                    // A plane tile: 128 rows * 64B
#define BPL    16384                   // B plane tile: 256 rows * 64B
#define BOFF   (3 * APL)               // 24576
#define STB    (3 * APL + 3 * BPL)     // 73728
#define SMEMT  (STAGES * STB)          // 221184

// fc1 (bf16x4 mma, split-K)
#define FC1KS   4
#define F1KC    (DTQ / FC1KS)          // 8192 K per split
#define F1NCH   (F1KC / KC)            // 256 chunks
#define F1TPL   8192                   // 128 rows * 64B per plane tile
#define F1STB   (4 * F1TPL)            // 32768 (Ap1,Ap2,Bp1,Bp2)
#define F1SMEM  (3 * F1STB)            // 98304

// k_scores dynamic smem: 3 th bufs + 3 ph bufs (8KB each) + sS (1KB)
#define SCTH    0
#define SCPH    24576
#define SCSS    49152
#define SCSMEM  (49152 + 1024)

// ---------------- device scratch ----------------
__device__ float g_inv [DQ];
__device__ float g_cadd[DQ];
__device__ float g_cc  [DQ];
__device__ float g_M   [(size_t)DQ * DQ];       // W_w @ g_w
__device__ float g_bc  [RWS];
__device__ float g_alpha[(size_t)BQ * 256];     // softmax alpha per batch [t][s]
__device__ __nv_bfloat16 g_Wp1[(size_t)RWS * DQ];   // folded weight planes
__device__ __nv_bfloat16 g_Wp2[(size_t)RWS * DQ];
__device__ __nv_bfloat16 g_Wp3[(size_t)RWS * DQ];
__device__ __nv_bfloat16 g_Hp1[(size_t)NTOT * DQ];  // h planes [n=b*16+t][k=d]
__device__ __nv_bfloat16 g_Hp2[(size_t)NTOT * DQ];
__device__ __nv_bfloat16 g_Hp3[(size_t)NTOT * DQ];
__device__ float g_C   [(size_t)BQ * CRW];      // projections [b][o][t]
__device__ __nv_bfloat16 g_Fp1[(size_t)BQ * DTQ];   // F planes (fc1 A operand)
__device__ __nv_bfloat16 g_Fp2[(size_t)BQ * DTQ];
__device__ __nv_bfloat16 g_W1a[(size_t)512 * DTQ];  // fc1 weight planes
__device__ __nv_bfloat16 g_W1b[(size_t)512 * DTQ];
__device__ float g_Y1  [(size_t)BQ * 512];
__device__ float g_Y1p [FC1KS][(size_t)BQ * 512];   // fc1 K-split partials

// ---------------- helpers ----------------
__device__ __forceinline__ uint32_t smem_u32(const void* p) {
    uint32_t a;
    asm("{ .reg .u64 t; cvta.to.shared.u64 t, %1; cvt.u32.u64 %0, t; }" : "=r"(a) : "l"(p));
    return a;
}

__device__ __forceinline__ void cp16(uint32_t dst, const void* src) {
    asm volatile("cp.async.cg.shared.global [%0], [%1], 16;" :: "r"(dst), "l"(src));
}
#define CP_COMMIT() asm volatile("cp.async.commit_group;" ::: "memory")
#define CP_WAIT1()  asm volatile("cp.async.wait_group 1;" ::: "memory")

__device__ __forceinline__ void ldm_x4(uint32_t* r, uint32_t addr) {
    asm volatile("ldmatrix.sync.aligned.m8n8.x4.shared.b16 {%0,%1,%2,%3}, [%4];"
                 : "=r"(r[0]), "=r"(r[1]), "=r"(r[2]), "=r"(r[3]) : "r"(addr));
}

__device__ __forceinline__ void mma16(float* c, const uint32_t* a, uint32_t b0, uint32_t b1) {
    asm volatile("mma.sync.aligned.m16n8k16.row.col.f32.bf16.bf16.f32 "
                 "{%0,%1,%2,%3},{%4,%5,%6,%7},{%8,%9},{%0,%1,%2,%3};"
                 : "+f"(c[0]), "+f"(c[1]), "+f"(c[2]), "+f"(c[3])
                 : "r"(a[0]), "r"(a[1]), "r"(a[2]), "r"(a[3]), "r"(b0), "r"(b1));
}

// 3-way bf16 split: v ~= b1 + b2 + b3
__device__ __forceinline__ void bsplit(float v, uint16_t& o1, uint16_t& o2, uint16_t& o3) {
    __nv_bfloat16 x1 = __float2bfloat16_rn(v);
    float r1 = v - __bfloat162float(x1);
    __nv_bfloat16 x2 = __float2bfloat16_rn(r1);
    float r2 = r1 - __bfloat162float(x2);
    __nv_bfloat16 x3 = __float2bfloat16_rn(r2);
    o1 = *(uint16_t*)&x1;
    o2 = *(uint16_t*)&x2;
    o3 = *(uint16_t*)&x3;
}

// 2-way bf16 split
__device__ __forceinline__ void bsplit2(float v, uint16_t& o1, uint16_t& o2) {
    __nv_bfloat16 x1 = __float2bfloat16_rn(v);
    float r1 = v - __bfloat162float(x1);
    __nv_bfloat16 x2 = __float2bfloat16_rn(r1);
    o1 = *(uint16_t*)&x1;
    o2 = *(uint16_t*)&x2;
}

__device__ __forceinline__ float bf2f(uint16_t u) {
    __nv_bfloat16 h = *(__nv_bfloat16*)&u;
    return __bfloat162float(h);
}

__device__ __forceinline__ void load4(const __nv_bfloat16* p, float* f) {
    uint2 u = *(const uint2*)p;
    const uint16_t* h = (const uint16_t*)&u;
    f[0] = bf2f(h[0]); f[1] = bf2f(h[1]); f[2] = bf2f(h[2]); f[3] = bf2f(h[3]);
}

// 64B-row XOR swizzle: conflict-free for 8-row ldmatrix and 16B fills
__device__ __forceinline__ uint32_t sw64(int row, int g) {
    return (uint32_t)(row * 64 + ((g ^ ((row >> 1) & 3)) << 4));
}

// ---------------- prep kernels ----------------
__global__ void k_bn_prep(const float* __restrict__ gamma, const float* __restrict__ beta,
                          const float* __restrict__ mean,  const float* __restrict__ var) {
    int d = blockIdx.x * blockDim.x + threadIdx.x;
    if (d < DQ) {
        float inv = gamma[d] * rsqrtf(var[d] + 1e-5f);
        float ca  = beta[d] - mean[d] * inv;
        g_inv[d]  = inv;
        g_cadd[d] = ca;
        g_cc[d]   = ca * (2.0f * inv + 1.0f);
    }
}

__global__ __launch_bounds__(256) void k_foldbias(
    const float* __restrict__ thw, const float* __restrict__ phw,
    const float* __restrict__ gamma, const float* __restrict__ beta,
    const float* __restrict__ mean,  const float* __restrict__ var) {
    const int o = blockIdx.x;
    const int tid = threadIdx.x;
    const float* row;
    if (o < 1024)      row = thw + (size_t)o * DQ;
    else if (o < 2048) row = phw + (size_t)(o - 1024) * DQ;
    else               row = g_M + (size_t)(o - 2048) * DQ;
    float accb = 0.f;
    for (int d = tid; d < DQ; d += 256) {
        float inv = gamma[d] * rsqrtf(var[d] + 1e-5f);
        float ca  = beta[d] - mean[d] * inv;
        float w   = row[d];
        float v   = w * inv;
        uint16_t b1, b2, b3;
        bsplit(v, b1, b2, b3);
        size_t idx = (size_t)o * DQ + d;
        *(uint16_t*)&g_Wp1[idx] = b1;
        *(uint16_t*)&g_Wp2[idx] = b2;
        *(uint16_t*)&g_Wp3[idx] = b3;
        accb += w * ca;
    }
    __shared__ float red[256];
    red[tid] = accb;
    __syncthreads();
    for (int st = 128; st > 0; st >>= 1) {
        if (tid < st) red[tid] += red[tid + st];
        __syncthreads();
    }
    if (tid == 0) g_bc[o] = red[0];
}

// Ht planes[n=b*16+t][k=d] = split(x[b*32768 + d*16 + t])
__global__ __launch_bounds__(256) void k_init(const float* __restrict__ x) {
    __shared__ float s[128 * 17];
    int b = blockIdx.x, tid = threadIdx.x;
    for (int d0 = 0; d0 < DQ; d0 += 128) {
        for (int i = tid; i < 2048; i += 256) {
            int dd = i >> 4, t = i & 15;
            s[dd * 17 + t] = x[(size_t)b * DTQ + d0 * 16 + i];
        }
        __syncthreads();
        int t = tid >> 4, j = tid & 15;
        size_t base = ((size_t)(b * 16 + t)) * DQ + d0 + j * 8;
#pragma unroll
        for (int i = 0; i < 8; i += 2) {
            float v0 = s[(j * 8 + i) * 17 + t];
            float v1 = s[(j * 8 + i + 1) * 17 + t];
            uint16_t a1, a2, a3, c1, c2, c3;
            bsplit(v0, a1, a2, a3);
            bsplit(v1, c1, c2, c3);
            *(uint32_t*)&g_Hp1[base + i] = (uint32_t)a1 | ((uint32_t)c1 << 16);
            *(uint32_t*)&g_Hp2[base + i] = (uint32_t)a2 | ((uint32_t)c2 << 16);
            *(uint32_t*)&g_Hp3[base + i] = (uint32_t)a3 | ((uint32_t)c3 << 16);
        }
        __syncthreads();
    }
}

// fc1 weight split into 2 bf16 planes
__global__ __launch_bounds__(256) void k_fc1split(const float* __restrict__ w) {
    const int r = blockIdx.x;
    for (int k = threadIdx.x; k < DTQ; k += 256) {
        float v = w[(size_t)r * DTQ + k];
        uint16_t b1, b2;
        bsplit2(v, b1, b2);
        *(uint16_t*)&g_W1a[(size_t)r * DTQ + k] = b1;
        *(uint16_t*)&g_W1b[(size_t)r * DTQ + k] = b2;
    }
}

// ---------------- M = W_w @ g_w (fp32 SIMT, run once) ----------------
__global__ __launch_bounds__(256) void k_gemm_M(const float* __restrict__ A,
                                                const float* __restrict__ B) {
    __shared__ float As[16][132];
    __shared__ float Bs[16][132];
    const int tid = threadIdx.x;
    const int rx  = tid & 15;
    const int ry  = tid >> 4;
    const int row0 = blockIdx.y * 128;
    const int col0 = blockIdx.x * 128;
    float acc[8][8];
#pragma unroll
    for (int i = 0; i < 8; i++)
#pragma unroll
        for (int j = 0; j < 8; j++) acc[i][j] = 0.f;
    for (int k0 = 0; k0 < DHQ; k0 += 16) {
#pragma unroll
        for (int f = tid; f < 512; f += 256) {
            int r = f >> 2, kk = (f & 3) << 2;
            float4 v = *(const float4*)(&A[(size_t)(row0 + r) * DHQ + k0 + kk]);
            As[kk + 0][r] = v.x; As[kk + 1][r] = v.y;
            As[kk + 2][r] = v.z; As[kk + 3][r] = v.w;
        }
#pragma unroll
        for (int f = tid; f < 512; f += 256) {
            int k = f >> 5, cc = (f & 31) << 2;
            float4 v = *(const float4*)(&B[(size_t)(k0 + k) * DQ + col0 + cc]);
            *(float4*)(&Bs[k][cc]) = v;
        }
        __syncthreads();
#pragma unroll
        for (int k = 0; k < 16; k++) {
            float ra[8], rb[8];
            *(float4*)(ra)     = *(const float4*)(&As[k][ry * 4]);
            *(float4*)(ra + 4) = *(const float4*)(&As[k][64 + ry * 4]);
            *(float4*)(rb)     = *(const float4*)(&Bs[k][rx * 4]);
            *(float4*)(rb + 4) = *(const float4*)(&Bs[k][64 + rx * 4]);
#pragma unroll
            for (int i = 0; i < 8; i++)
#pragma unroll
                for (int j = 0; j < 8; j++) acc[i][j] += ra[i] * rb[j];
        }
        __syncthreads();
    }
#pragma unroll
    for (int ih = 0; ih < 2; ih++)
#pragma unroll
        for (int i = 0; i < 4; i++) {
            const int r = row0 + ih * 64 + ry * 4 + i;
#pragma unroll
            for (int jh = 0; jh < 2; jh++) {
                const int c = col0 + jh * 64 + rx * 4;
                float4 v;
                v.x = acc[ih * 4 + i][jh * 4 + 0];
                v.y = acc[ih * 4 + i][jh * 4 + 1];
                v.z = acc[ih * 4 + i][jh * 4 + 2];
                v.w = acc[ih * 4 + i][jh * 4 + 3];
                *(float4*)(&g_M[(size_t)r * DQ + c]) = v;
            }
        }
}

// ---------------- bf16x6 mma GEMM: C[b][o][t] = sum_k Wc[o][k]*Ht[n][k] + bc[o] ----------------
// Block 128x256, 16 warps (warp 32x64), 3-stage cp.async pipeline, ONE sync per chunk,
// direct-scatter epilogue. (round-14/16 verified fastest configuration — FROZEN)
__global__ __launch_bounds__(512, 1) void k_gemm_mma() {
    extern __shared__ __align__(128) char smem[];
    const uint32_t sb = smem_u32(smem);
    const int tid  = threadIdx.x;
    const int wid  = tid >> 5;
    const int lane = tid & 31;
    const int m0 = blockIdx.x * MT;
    const int n0 = blockIdx.y * NT;
    const int warp_m = (wid & 3) * 32;
    const int warp_n = (wid >> 2) * 64;

    const int frow = tid >> 2;          // 0..127
    const int fgr  = tid & 3;
    const uint32_t soA = sw64(frow, fgr);

    float acc[2][8][4];
#pragma unroll
    for (int i = 0; i < 2; i++)
#pragma unroll
        for (int j = 0; j < 8; j++)
#pragma unroll
            for (int k = 0; k < 4; k++) acc[i][j][k] = 0.f;

    const __nv_bfloat16* Wp[3] = {g_Wp1, g_Wp2, g_Wp3};
    const __nv_bfloat16* Hp[3] = {g_Hp1, g_Hp2, g_Hp3};

    auto issue = [&](int c, int st) {
        const uint32_t base = sb + st * STB;
        const int k0 = c * KC;
        const size_t aoff = (size_t)(m0 + frow) * DQ + k0 + fgr * 8;
        const size_t boff = (size_t)(n0 + frow) * DQ + k0 + fgr * 8;
        const size_t boff2 = boff + (size_t)128 * DQ;
#pragma unroll
        for (int p = 0; p < 3; p++)
            cp16(base + p * APL + soA, Wp[p] + aoff);
#pragma unroll
        for (int p = 0; p < 3; p++) {
            cp16(base + BOFF + p * BPL + soA,        Hp[p] + boff);
            cp16(base + BOFF + p * BPL + soA + 8192, Hp[p] + boff2);
        }
    };

    issue(0, 0); CP_COMMIT();
    issue(1, 1); CP_COMMIT();

    const int lt = lane >> 3;
    const int lr = lane & 7;
    const int aR  = ((lt & 1) << 3) + lr;
    const int aGs = lt >> 1;
    const int bR  = ((lt >> 1) << 3) + lr;
    const int bGs = lt & 1;

#pragma unroll 1
    for (int c = 0; c < NCH; c++) {
        CP_WAIT1();
        __syncthreads();

        const uint32_t base = sb + (c % STAGES) * STB;

#pragma unroll
        for (int kk = 0; kk < 2; kk++) {
            uint32_t af[3][2][4];
#pragma unroll
            for (int p = 0; p < 3; p++)
#pragma unroll
                for (int mt = 0; mt < 2; mt++)
                    ldm_x4(af[p][mt],
                           base + p * APL + sw64(warp_m + mt * 16 + aR, kk * 2 + aGs));
#pragma unroll
            for (int half = 0; half < 2; half++) {
#pragma unroll
                for (int pb = 0; pb < 3; pb++) {
                    uint32_t bf[2][4];
#pragma unroll
                    for (int qq = 0; qq < 2; qq++)
                        ldm_x4(bf[qq],
                               base + BOFF + pb * BPL +
                               sw64(warp_n + (half * 2 + qq) * 16 + bR, kk * 2 + bGs));
                    const int napr = 3 - pb;
#pragma unroll
                    for (int pa = 0; pa < 3; pa++) {
                        if (pa < napr) {
#pragma unroll
                            for (int mt = 0; mt < 2; mt++)
#pragma unroll
                                for (int nt = 0; nt < 4; nt++) {
                                    const int s = (nt & 1) * 2;
                                    mma16(acc[mt][half * 4 + nt], af[pa][mt],
                                          bf[nt >> 1][s], bf[nt >> 1][s + 1]);
                                }
                        }
                    }
                }
            }
        }

        if (c + 2 < NCH) issue(c + 2, (c + 2) % STAGES);
        CP_COMMIT();
    }

    // direct-scatter epilogue: C[b][o][t] with bias
#pragma unroll
    for (int mt = 0; mt < 2; mt++) {
        const int R0 = m0 + warp_m + mt * 16 + (lane >> 2);
        const float b0v = g_bc[R0];
        const float b1v = g_bc[R0 + 8];
#pragma unroll
        for (int nt = 0; nt < 8; nt++) {
            const int col = n0 + warp_n + nt * 8 + 2 * (lane & 3);
            const int bb = col >> 4;
            const int t  = col & 15;
            float2 v0 = make_float2(acc[mt][nt][0] + b0v, acc[mt][nt][1] + b0v);
            float2 v1 = make_float2(acc[mt][nt][2] + b1v, acc[mt][nt][3] + b1v);
            *(float2*)(&g_C[(size_t)bb * CRW + R0 * 16 + t])       = v0;
            *(float2*)(&g_C[(size_t)bb * CRW + (R0 + 8) * 16 + t]) = v1;
        }
    }
}

// ---------------- scores + softmax (per batch item), 3-buffer cp.async pipeline ----------------
// Prefetch distance 2, wait_group 1, issue-before-compute: hides chunk load latency.
// Summation order identical to previous rounds (k serial per chunk, chunks serial).
__global__ __launch_bounds__(256) void k_scores() {
    extern __shared__ __align__(16) char ssm[];
    const int b = blockIdx.x;
    const int tid = threadIdx.x;
    const float* Cb = g_C + (size_t)b * CRW;

    float* sth = (float*)(ssm + SCTH);    // 3 x 2048 floats
    float* sph = (float*)(ssm + SCPH);    // 3 x 2048 floats
    float* sS  = (float*)(ssm + SCSS);    // 16 x 16
    const uint32_t a_th = smem_u32(sth);
    const uint32_t a_ph = smem_u32(sph);

    const int t16 = tid >> 4;
    const int s16 = tid & 15;
    const int g0 = tid * 2;   // two 16B granules per thread per tile

    auto issueS = [&](int c) {
        const int buf = c % 3;
        const float* srcT = Cb + c * 2048;
        const float* srcP = Cb + DHQ * 16 + c * 2048;
        cp16(a_th + buf * 8192 + g0 * 16,      srcT + g0 * 4);
        cp16(a_th + buf * 8192 + g0 * 16 + 16, srcT + g0 * 4 + 4);
        cp16(a_ph + buf * 8192 + g0 * 16,      srcP + g0 * 4);
        cp16(a_ph + buf * 8192 + g0 * 16 + 16, srcP + g0 * 4 + 4);
    };

    issueS(0); CP_COMMIT();
    issueS(1); CP_COMMIT();

    float acc = 0.f;
    for (int c = 0; c < 8; c++) {
        CP_WAIT1();              // group c complete (c+1 may remain in flight)
        __syncthreads();         // publish all threads' copies of buf c%3
        if (c + 2 < 8) { issueS(c + 2); CP_COMMIT(); }   // overwrites buf (c-1)%3: safe
        const int buf = c % 3;
#pragma unroll 8
        for (int k = 0; k < 128; k++)
            acc += sth[buf * 2048 + k * 16 + t16] * sph[buf * 2048 + k * 16 + s16];
    }
    __syncthreads();
    sS[t16 * 16 + s16] = acc * (1.0f / (float)DHQ);
    __syncthreads();

    if (tid < 16) {
        float mx = sS[tid * 16];
#pragma unroll
        for (int j = 1; j < 16; j++) mx = fmaxf(mx, sS[tid * 16 + j]);
        float e[16], sum = 0.f;
#pragma unroll
        for (int j = 0; j < 16; j++) { e[j] = expf(sS[tid * 16 + j] - mx); sum += e[j]; }
        float rs = 1.0f / sum;
#pragma unroll
        for (int j = 0; j < 16; j++) g_alpha[(size_t)b * 256 + tid * 16 + j] = e[j] * rs;
    }
}

// ---------------- residual update: H' = i2*(G alpha^T) + (1+i2)*H + cc ----------------
__global__ __launch_bounds__(256) void k_update() {
    const int dblk = blockIdx.x;        // 0..7 (256 d each)
    const int b    = blockIdx.y;
    const int tid  = threadIdx.x;
    const float* Cb = g_C + (size_t)b * CRW;

    __shared__ float sA[256];
    __shared__ float sg[256][17];

    sA[tid] = g_alpha[(size_t)b * 256 + tid];
#pragma unroll
    for (int i = tid; i < 1024; i += 256) {
        const int r  = i >> 2;
        const int c4 = i & 3;
        float4 v = ((const float4*)(Cb + (size_t)(2048 + dblk * 256 + r) * 16))[c4];
        sg[r][c4 * 4 + 0] = v.x;
        sg[r][c4 * 4 + 1] = v.y;
        sg[r][c4 * 4 + 2] = v.z;
        sg[r][c4 * 4 + 3] = v.w;
    }
    __syncthreads();

    const int tg   = tid >> 6;
    const int dg   = tid & 63;
    const int dloc = dg * 4;
    const int d    = dblk * 256 + dloc;

    float inv4[4], cc4[4], i24[4];
    *(float4*)inv4 = *(const float4*)(&g_inv[d]);
    *(float4*)cc4  = *(const float4*)(&g_cc[d]);
#pragma unroll
    for (int i = 0; i < 4; i++) i24[i] = inv4[i] * inv4[i];

#pragma unroll
    for (int tt = 0; tt < 4; tt++) {
        const int t = tg * 4 + tt;
        const size_t hidx = ((size_t)(b * 16 + t)) * DQ + d;
        float f1[4], f2[4], f3[4];
        load4(&g_Hp1[hidx], f1);
        load4(&g_Hp2[hidx], f2);
        load4(&g_Hp3[hidx], f3);
        uint16_t o1[4], o2[4], o3[4];
#pragma unroll
        for (int i = 0; i < 4; i++) {
            const float h = f1[i] + f2[i] + f3[i];
            float c1 = 0.f;
#pragma unroll
            for (int s = 0; s < 16; s++) c1 += sA[t * 16 + s] * sg[dloc + i][s];
            const float v = i24[i] * c1 + (1.0f + i24[i]) * h + cc4[i];
            bsplit(v, o1[i], o2[i], o3[i]);
        }
        *(uint2*)&g_Hp1[hidx] = make_uint2((uint32_t)o1[0] | ((uint32_t)o1[1] << 16),
                                           (uint32_t)o1[2] | ((uint32_t)o1[3] << 16));
        *(uint2*)&g_Hp2[hidx] = make_uint2((uint32_t)o2[0] | ((uint32_t)o2[1] << 16),
                                           (uint32_t)o2[2] | ((uint32_t)o2[3] << 16));
        *(uint2*)&g_Hp3[hidx] = make_uint2((uint32_t)o3[0] | ((uint32_t)o3[1] << 16),
                                           (uint32_t)o3[2] | ((uint32_t)o3[3] << 16));
    }
}

// ---------------- final: Fp = split2(relu(BN(h)+x)), layout transpose ----------
__global__ __launch_bounds__(256) void k_final(const float* __restrict__ x) {
    __shared__ float s[16][132];
    const int b = blockIdx.x >> 4;
    const int q = blockIdx.x & 15;
    const int tid = threadIdx.x;

    const int tt = tid >> 4;
    const int ug = (tid & 15);
    const size_t base = ((size_t)(b * 16 + tt)) * DQ + q * 128;
#pragma unroll
    for (int r = 0; r < 2; r++) {
        const int uu = ug * 8 + r * 4;
        float f1[4], f2[4], f3[4];
        load4(&g_Hp1[base + uu], f1);
        load4(&g_Hp2[base + uu], f2);
        load4(&g_Hp3[base + uu], f3);
        float4 inv4 = *(const float4*)(&g_inv[q * 128 + uu]);
        float4 ca4  = *(const float4*)(&g_cadd[q * 128 + uu]);
        s[tt][uu + 0] = inv4.x * (f1[0] + f2[0] + f3[0]) + ca4.x;
        s[tt][uu + 1] = inv4.y * (f1[1] + f2[1] + f3[1]) + ca4.y;
        s[tt][uu + 2] = inv4.z * (f1[2] + f2[2] + f3[2]) + ca4.z;
        s[tt][uu + 3] = inv4.w * (f1[3] + f2[3] + f3[3]) + ca4.w;
    }
    __syncthreads();

    const size_t f0 = (size_t)b * DTQ + q * 2048;
    const int o0 = tid * 8;
    float4 xa = *(const float4*)(&x[f0 + o0]);
    float4 xb = *(const float4*)(&x[f0 + o0 + 4]);
    float vo[8];
#pragma unroll
    for (int r = 0; r < 8; r++) {
        const int o = o0 + r;
        vo[r] = s[o & 15][o >> 4];
    }
    const float xr[8] = {xa.x, xa.y, xa.z, xa.w, xb.x, xb.y, xb.z, xb.w};
    uint16_t p1[8], p2[8];
#pragma unroll
    for (int r = 0; r < 8; r++) {
        float v = fmaxf(vo[r] + xr[r], 0.f);
        bsplit2(v, p1[r], p2[r]);
    }
    *(uint2*)&g_Fp1[f0 + o0]     = make_uint2((uint32_t)p1[0] | ((uint32_t)p1[1] << 16),
                                              (uint32_t)p1[2] | ((uint32_t)p1[3] << 16));
    *(uint2*)&g_Fp1[f0 + o0 + 4] = make_uint2((uint32_t)p1[4] | ((uint32_t)p1[5] << 16),
                                              (uint32_t)p1[6] | ((uint32_t)p1[7] << 16));
    *(uint2*)&g_Fp2[f0 + o0]     = make_uint2((uint32_t)p2[0] | ((uint32_t)p2[1] << 16),
                                              (uint32_t)p2[2] | ((uint32_t)p2[3] << 16));
    *(uint2*)&g_Fp2[f0 + o0 + 4] = make_uint2((uint32_t)p2[4] | ((uint32_t)p2[5] << 16),
                                              (uint32_t)p2[6] | ((uint32_t)p2[7] << 16));
}

// ---------------- fc1 bf16x4 mma partials: Y1p[ks] = F @ fc1_w^T (K slice) ----------------
__global__ __launch_bounds__(256, 1) void k_fc1mma() {
    extern __shared__ __align__(128) char smem[];
    const uint32_t sb = smem_u32(smem);
    const int tid  = threadIdx.x;
    const int wid  = tid >> 5;
    const int lane = tid & 31;
    const int n0 = blockIdx.x * 128;
    const int m0 = blockIdx.y * 128;
    const int ks = blockIdx.z;
    const int kbeg = ks * F1KC;
    const int warp_m = (wid & 3) * 32;
    const int warp_n = (wid >> 2) * 64;

    const int frow = tid >> 1;          // 0..127
    const int fg   = (tid & 1) * 2;     // granules fg, fg+1

    float acc[2][8][4];
#pragma unroll
    for (int i = 0; i < 2; i++)
#pragma unroll
        for (int j = 0; j < 8; j++)
#pragma unroll
            for (int k = 0; k < 4; k++) acc[i][j][k] = 0.f;

    const __nv_bfloat16* Ap[2] = {g_Fp1, g_Fp2};
    const __nv_bfloat16* Bp[2] = {g_W1a, g_W1b};

    auto issue = [&](int c, int st) {
        const uint32_t base = sb + st * F1STB;
        const int k0 = kbeg + c * KC;
        const size_t aoff = (size_t)(m0 + frow) * DTQ + k0 + fg * 8;
        const size_t boff = (size_t)(n0 + frow) * DTQ + k0 + fg * 8;
        const uint32_t so0 = sw64(frow, fg);
        const uint32_t so1 = sw64(frow, fg + 1);
#pragma unroll
        for (int p = 0; p < 2; p++) {
            cp16(base + p * F1TPL + so0, Ap[p] + aoff);
            cp16(base + p * F1TPL + so1, Ap[p] + aoff + 8);
            cp16(base + (2 + p) * F1TPL + so0, Bp[p] + boff);
            cp16(base + (2 + p) * F1TPL + so1, Bp[p] + boff + 8);
        }
    };

    issue(0, 0); CP_COMMIT();
    issue(1, 1); CP_COMMIT();

    const int lt = lane >> 3;
    const int lr = lane & 7;
    const int aR  = ((lt & 1) << 3) + lr;
    const int aGs = lt >> 1;
    const int bR  = ((lt >> 1) << 3) + lr;
    const int bGs = lt & 1;

#pragma unroll 1
    for (int c = 0; c < F1NCH; c++) {
        CP_WAIT1();
        __syncthreads();

        const uint32_t base = sb + (c % 3) * F1STB;

#pragma unroll
        for (int kk = 0; kk < 2; kk++) {
            uint32_t af[2][2][4];
#pragma unroll
            for (int p = 0; p < 2; p++)
#pragma unroll
                for (int mt = 0; mt < 2; mt++)
                    ldm_x4(af[p][mt],
                           base + p * F1TPL + sw64(warp_m + mt * 16 + aR, kk * 2 + aGs));
            uint32_t bfr[2][4][4];
#pragma unroll
            for (int p = 0; p < 2; p++)
#pragma unroll
                for (int q = 0; q < 4; q++)
                    ldm_x4(bfr[p][q],
                           base + (2 + p) * F1TPL +
                           sw64(warp_n + q * 16 + bR, kk * 2 + bGs));
#pragma unroll
            for (int mt = 0; mt < 2; mt++)
#pragma unroll
                for (int nt = 0; nt < 8; nt++) {
                    const int pq = nt >> 1;
                    const int s  = (nt & 1) * 2;
                    float* C = acc[mt][nt];
                    mma16(C, af[1][mt], bfr[0][pq][s], bfr[0][pq][s + 1]);   // A2B1
                    mma16(C, af[0][mt], bfr[1][pq][s], bfr[1][pq][s + 1]);   // A1B2
                    mma16(C, af[0][mt], bfr[0][pq][s], bfr[0][pq][s + 1]);   // A1B1
                }
        }

        if (c + 2 < F1NCH) issue(c + 2, (c + 2) % 3);
        CP_COMMIT();
    }

    float* Yp = g_Y1p[ks];
#pragma unroll
    for (int mt = 0; mt < 2; mt++) {
        const int R0 = m0 + warp_m + mt * 16 + (lane >> 2);
#pragma unroll
        for (int nt = 0; nt < 8; nt++) {
            const int col = n0 + warp_n + nt * 8 + 2 * (lane & 3);
            *(float2*)(&Yp[(size_t)R0 * 512 + col]) =
                make_float2(acc[mt][nt][0], acc[mt][nt][1]);
            *(float2*)(&Yp[(size_t)(R0 + 8) * 512 + col]) =
                make_float2(acc[mt][nt][2], acc[mt][nt][3]);
        }
    }
}

// reduce partials + bias + relu
__global__ void k_fc1red(const float* __restrict__ bias) {
    const size_t i4 = (size_t)blockIdx.x * blockDim.x + threadIdx.x;
    const size_t i  = i4 * 4;
    const int c = (int)(i & 511);
    float4 a = *(const float4*)(&g_Y1p[0][i]);
    float4 b = *(const float4*)(&g_Y1p[1][i]);
    float4 cc = *(const float4*)(&g_Y1p[2][i]);
    float4 d = *(const float4*)(&g_Y1p[3][i]);
    float4 bb = *(const float4*)(&bias[c]);
    float4 v;
    v.x = fmaxf(a.x + b.x + cc.x + d.x + bb.x, 0.f);
    v.y = fmaxf(a.y + b.y + cc.y + d.y + bb.y, 0.f);
    v.z = fmaxf(a.z + b.z + cc.z + d.z + bb.z, 0.f);
    v.w = fmaxf(a.w + b.w + cc.w + d.w + bb.w, 0.f);
    *(float4*)(&g_Y1[i]) = v;
}

// ---------------- fc2 ----------------
__global__ void k_fc2(const float* __restrict__ w, const float* __restrict__ bias,
                      float* __restrict__ out) {
    const int b = blockIdx.x;
    __shared__ float sy[512];
    for (int i = threadIdx.x; i < 512; i += blockDim.x) sy[i] = g_Y1[(size_t)b * 512 + i];
    __syncthreads();
    for (int c = threadIdx.x; c < NCQ; c += blockDim.x) {
        float acc = bias[c];
        const float* wr = w + (size_t)c * 512;
#pragma unroll 8
        for (int n = 0; n < 512; n++) acc += sy[n] * wr[n];
        out[(size_t)b * NCQ + c] = acc;
    }
}

// ---------------- launch ----------------
extern "C" void kernel_launch(void* const* d_in, const int* in_sizes, int n_in,
                              void* d_out, int out_size) {
    const float* x     = (const float*)d_in[0];
    const float* thw   = (const float*)d_in[1];
    const float* phw   = (const float*)d_in[2];
    const float* gw    = (const float*)d_in[3];
    const float* Ww    = (const float*)d_in[4];
    const float* gamma = (const float*)d_in[5];
    const float* beta  = (const float*)d_in[6];
    const float* mean  = (const float*)d_in[7];
    const float* var   = (const float*)d_in[8];
    const float* fc1w  = (const float*)d_in[9];
    const float* fc1b  = (const float*)d_in[10];
    const float* fc2w  = (const float*)d_in[11];
    const float* fc2b  = (const float*)d_in[12];
    float* out = (float*)d_out;

    cudaFuncSetAttribute(k_gemm_mma, cudaFuncAttributeMaxDynamicSharedMemorySize, SMEMT);
    cudaFuncSetAttribute(k_fc1mma, cudaFuncAttributeMaxDynamicSharedMemorySize, F1SMEM);
    cudaFuncSetAttribute(k_scores, cudaFuncAttributeMaxDynamicSharedMemorySize, SCSMEM);

    // launch order arranged so the 4th launch is k_gemm_mma (ncu capture slot)
    k_gemm_M<<<dim3(DQ / 128, DQ / 128), 256>>>(Ww, gw);            // 1
    k_init<<<BQ, 256>>>(x);                                         // 2
    k_foldbias<<<RWS, 256>>>(thw, phw, gamma, beta, mean, var);     // 3
    k_gemm_mma<<<dim3(RWS / MT, NTOT / NT), 512, SMEMT>>>();        // 4 <- profile
    k_bn_prep<<<(DQ + 255) / 256, 256>>>(gamma, beta, mean, var);   // 5
    k_scores<<<BQ, 256, SCSMEM>>>();                                // 6
    k_update<<<dim3(8, BQ), 256>>>();                               // 7

    for (int it = 1; it < TQ; ++it) {
        k_gemm_mma<<<dim3(RWS / MT, NTOT / NT), 512, SMEMT>>>();
        k_scores<<<BQ, 256, SCSMEM>>>();
        k_update<<<dim3(8, BQ), 256>>>();
    }

    k_fc1split<<<512, 256>>>(fc1w);
    k_final<<<BQ * 16, 256>>>(x);
    k_fc1mma<<<dim3(4, BQ / 128, FC1KS), 256, F1SMEM>>>();
    k_fc1red<<<(BQ * 512 / 4) / 256, 256>>>(fc1b);
    k_fc2<<<BQ, 256>>>(fc2w, fc2b, out);
}